// round 13
// baseline (speedup 1.0000x reference)
#include <cuda_runtime.h>
#include <cuda_bf16.h>
#include <math.h>
#include <stdint.h>

// ---------------- problem constants ----------------
constexpr int kV   = 50280;
constexpr int kD   = 768;
constexpr int kNL  = 8;
constexpr int kDI  = 1536;
constexpr int kDS  = 16;
constexpr int kDC  = 4;
constexpr int kDTR = 48;
constexpr int kNC  = 4;
constexpr int kB   = 2;
constexpr int kL   = 1024;
constexpr int kDBC = kDTR + 2 * kDS;  // 80
constexpr float kEPS = 1e-5f;

constexpr int kRows = kB * kL;        // 2048
constexpr int kXPChunks = 8;
constexpr int kXPKC = kDI / kXPChunks; // 192

// chunked scan
constexpr int kG   = 32;
constexpr int kNCH = kL / kG;         // 32
constexpr int kScanN = kB * kNCH * kDI * kDS;   // 1.57M

constexpr int kInWN  = kNL * 2 * kDI * kD;   // 18.9M
constexpr int kOutWN = kNL * kD * kDI;       // 9.4M

// ---------------- device scratch ----------------
__device__ float g_x  [kRows * kD];
__device__ float g_xn [kRows * kD];          // fp32 (final norm only)
__device__ float g_xz [kRows * 2 * kDI];
__device__ float g_xc [kRows * kDI];
__device__ float g_dbc[kRows * kDBC];
__device__ float g_dbp[kXPChunks * kRows * kDBC];
__device__ float g_dt [kRows * kDI];
__device__ float g_E  [kScanN];
__device__ float g_U  [kScanN];
__device__ float g_H  [kScanN];

__device__ __align__(16) __nv_bfloat16 g_winh[kInWN];
__device__ __align__(16) __nv_bfloat16 g_winl[kInWN];
__device__ __align__(16) __nv_bfloat16 g_wouth[kOutWN];
__device__ __align__(16) __nv_bfloat16 g_woutl[kOutWN];
__device__ __align__(16) __nv_bfloat16 g_xnh[kRows * kD];
__device__ __align__(16) __nv_bfloat16 g_yh [kRows * kDI];

// ---------------- helpers ----------------
__device__ __forceinline__ float warp_sum(float v) {
#pragma unroll
    for (int o = 16; o > 0; o >>= 1) v += __shfl_xor_sync(0xffffffffu, v, o);
    return v;
}
__device__ __forceinline__ uint32_t smem_u32(const void* p) {
    return (uint32_t)__cvta_generic_to_shared(p);
}
__device__ __forceinline__ void ldmat_x4(uint32_t& r0, uint32_t& r1,
                                         uint32_t& r2, uint32_t& r3,
                                         uint32_t addr) {
    asm volatile("ldmatrix.sync.aligned.m8n8.x4.shared.b16 {%0,%1,%2,%3}, [%4];"
                 : "=r"(r0), "=r"(r1), "=r"(r2), "=r"(r3) : "r"(addr));
}
__device__ __forceinline__ void mma16816(float* c, const uint32_t* a,
                                         uint32_t b0, uint32_t b1) {
    asm volatile(
        "mma.sync.aligned.m16n8k16.row.col.f32.bf16.bf16.f32 "
        "{%0,%1,%2,%3}, {%4,%5,%6,%7}, {%8,%9}, {%0,%1,%2,%3};"
        : "+f"(c[0]), "+f"(c[1]), "+f"(c[2]), "+f"(c[3])
        : "r"(a[0]), "r"(a[1]), "r"(a[2]), "r"(a[3]), "r"(b0), "r"(b1));
}
__device__ __forceinline__ void cp16(uint32_t dst, const void* src) {
    asm volatile("cp.async.cg.shared.global [%0], [%1], 16;\n" :: "r"(dst), "l"(src));
}
__device__ __forceinline__ void cp_commit() {
    asm volatile("cp.async.commit_group;\n");
}
template <int N>
__device__ __forceinline__ void cp_wait() {
    asm volatile("cp.async.wait_group %0;\n" :: "n"(N));
}

// ---------------- weight hi/lo split ----------------
__global__ void split_f32_kernel(const float* __restrict__ src,
                                 __nv_bfloat16* __restrict__ h,
                                 __nv_bfloat16* __restrict__ l, int n4) {
    int i = blockIdx.x * blockDim.x + threadIdx.x;
    if (i >= n4) return;
    float4 v = ((const float4*)src)[i];
    __nv_bfloat162 h01 = __floats2bfloat162_rn(v.x, v.y);
    __nv_bfloat162 h23 = __floats2bfloat162_rn(v.z, v.w);
    __nv_bfloat162 l01 = __floats2bfloat162_rn(v.x - __bfloat162float(h01.x),
                                               v.y - __bfloat162float(h01.y));
    __nv_bfloat162 l23 = __floats2bfloat162_rn(v.z - __bfloat162float(h23.x),
                                               v.w - __bfloat162float(h23.y));
    ((__nv_bfloat162*)h)[i * 2]     = h01;
    ((__nv_bfloat162*)h)[i * 2 + 1] = h23;
    ((__nv_bfloat162*)l)[i * 2]     = l01;
    ((__nv_bfloat162*)l)[i * 2 + 1] = l23;
}

// ---------------- embed gather ----------------
__global__ void embed_kernel(const int* __restrict__ ids,
                             const float* __restrict__ embed,
                             float* __restrict__ x) {
    int idx = blockIdx.x * blockDim.x + threadIdx.x;
    int total = kRows * kD / 4;
    if (idx >= total) return;
    int row = idx / (kD / 4);
    int d4 = idx - row * (kD / 4);
    const float4* src = (const float4*)(embed + (size_t)ids[row] * kD);
    ((float4*)x)[idx] = src[d4];
}

// ---------------- rmsnorm: SPLIT -> bf16 hi plane; else fp32 ----------------
template <bool SPLIT>
__global__ void rmsnorm_kernel(const float* __restrict__ x,
                               const float* __restrict__ w,
                               float* __restrict__ outf,
                               __nv_bfloat16* __restrict__ outh) {
    int row = blockIdx.x;
    const float* xr = x + (size_t)row * kD;
    float s = 0.f;
    for (int d = threadIdx.x; d < kD; d += blockDim.x) {
        float v = xr[d];
        s = fmaf(v, v, s);
    }
    s = warp_sum(s);
    __shared__ float sh[8];
    __shared__ float inv_s;
    int wid = threadIdx.x >> 5, lane = threadIdx.x & 31;
    if (lane == 0) sh[wid] = s;
    __syncthreads();
    if (wid == 0) {
        float t = (lane < (blockDim.x >> 5)) ? sh[lane] : 0.f;
        t = warp_sum(t);
        if (lane == 0) inv_s = rsqrtf(t / (float)kD + kEPS);
    }
    __syncthreads();
    float inv = inv_s;
    for (int d = threadIdx.x; d < kD; d += blockDim.x) {
        float v = xr[d] * inv * w[d];
        if (SPLIT) outh[(size_t)row * kD + d] = __float2bfloat16_rn(v);
        else       outf[(size_t)row * kD + d] = v;
    }
}

// =====================================================================
// Pre-split bf16 tensor-core GEMM, 3-stage cp.async, single sync/kt.
//   C[M,N] = Ah[M,K] @ (Bh + Bl)[N,K]^T    (round-10/12 numerics)
//   BM in {64,128}, BN=128, BK=32, 256 threads (8 warps: 2 in M, 4 in N)
// EPI 0: store    EPI 1: C += result
// =====================================================================
template <int EPI, int BM>
__global__ __launch_bounds__(256, 2)
void hgemm_ps_kernel(const __nv_bfloat16* __restrict__ Ah,
                     const __nv_bfloat16* __restrict__ Bh,
                     const __nv_bfloat16* __restrict__ Bl,
                     float* __restrict__ C, int ldc, int K) {
    constexpr int BN = 128, BK = 32;
    constexpr int STR = 40;
    constexpr int WM = BM / 2;
    constexpr int MF = WM / 16;
    constexpr int ASZ = BM * STR;
    constexpr int BSZ = BN * STR;
    constexpr int ACH = BM / 64;        // A cp16 per thread (1 or 2)
    constexpr int ST = 3;               // pipeline stages

    extern __shared__ __nv_bfloat16 sm[];
    __nv_bfloat16* As_h = sm;                    // [ST][ASZ]
    __nv_bfloat16* Bs_h = As_h + ST * ASZ;       // [ST][BSZ]
    __nv_bfloat16* Bs_l = Bs_h + ST * BSZ;       // [ST][BSZ]

    const int tid = threadIdx.x;
    const int wid = tid >> 5, lane = tid & 31;
    const int bm0 = blockIdx.y * BM;
    const int bn0 = blockIdx.x * BN;
    const int wm = wid & 1;
    const int wn = wid >> 1;

    float acc[MF][4][4];
#pragma unroll
    for (int i = 0; i < MF; i++)
#pragma unroll
        for (int j = 0; j < 4; j++)
#pragma unroll
            for (int v = 0; v < 4; v++) acc[i][j][v] = 0.f;

    auto issue_loads = [&](int buf, int k0) {
#pragma unroll
        for (int u = 0; u < ACH; u++) {
            int id = tid + u * 256;
            int r = id >> 2, c8 = (id & 3) * 8;
            size_t g = (size_t)(bm0 + r) * K + k0 + c8;
            cp16(smem_u32(As_h + buf * ASZ + r * STR + c8), Ah + g);
        }
#pragma unroll
        for (int u = 0; u < 2; u++) {
            int id = tid + u * 256;
            int r = id >> 2, c8 = (id & 3) * 8;
            size_t g = (size_t)(bn0 + r) * K + k0 + c8;
            uint32_t soff = (uint32_t)(buf * BSZ + r * STR + c8);
            cp16(smem_u32(Bs_h + soff), Bh + g);
            cp16(smem_u32(Bs_l + soff), Bl + g);
        }
    };

    const int a_row = wm * WM + (lane & 15);
    const int a_col8 = (lane >> 4) << 3;
    const int b_grp = lane >> 3;
    const int b_row = wn * 32 + ((b_grp >> 1) << 3) + (lane & 7);
    const int b_col8 = (b_grp & 1) << 3;

    const int KT = K / BK;
    // prologue: fill 2 stages
    issue_loads(0, 0);
    cp_commit();
    if (KT > 1) { issue_loads(1, BK); cp_commit(); }

    for (int kt = 0; kt < KT; kt++) {
        if (kt + 1 < KT) cp_wait<1>(); else cp_wait<0>();
        __syncthreads();                // compute(kt-1) finished by all warps
        if (kt + 2 < KT) {
            issue_loads((kt + 2) % ST, (kt + 2) * BK);
            cp_commit();
        }
        const int buf = kt % ST;

#pragma unroll
        for (int kk = 0; kk < 2; kk++) {
            uint32_t ah[MF][4];
            uint32_t bh[4][2], bl[4][2];
#pragma unroll
            for (int i = 0; i < MF; i++) {
                uint32_t off = (uint32_t)(buf * ASZ + (a_row + i * 16) * STR
                                          + kk * 16 + a_col8);
                ldmat_x4(ah[i][0], ah[i][1], ah[i][2], ah[i][3],
                         smem_u32(As_h + off));
            }
#pragma unroll
            for (int jj = 0; jj < 2; jj++) {
                uint32_t off = (uint32_t)(buf * BSZ + (b_row + jj * 16) * STR
                                          + kk * 16 + b_col8);
                ldmat_x4(bh[jj * 2][0], bh[jj * 2][1],
                         bh[jj * 2 + 1][0], bh[jj * 2 + 1][1],
                         smem_u32(Bs_h + off));
                ldmat_x4(bl[jj * 2][0], bl[jj * 2][1],
                         bl[jj * 2 + 1][0], bl[jj * 2 + 1][1],
                         smem_u32(Bs_l + off));
            }
#pragma unroll
            for (int i = 0; i < MF; i++)
#pragma unroll
                for (int j = 0; j < 4; j++) {
                    mma16816(acc[i][j], ah[i], bh[j][0], bh[j][1]);
                    mma16816(acc[i][j], ah[i], bl[j][0], bl[j][1]);
                }
        }
    }

    const int c_row = bm0 + wm * WM + (lane >> 2);
    const int c_col = bn0 + wn * 32 + (lane & 3) * 2;
#pragma unroll
    for (int i = 0; i < MF; i++) {
#pragma unroll
        for (int j = 0; j < 4; j++) {
#pragma unroll
            for (int half = 0; half < 2; half++) {
                int gm = c_row + i * 16 + half * 8;
                int gn = c_col + j * 8;
                float* cp = C + (size_t)gm * ldc + gn;
                float v0 = acc[i][j][half * 2 + 0];
                float v1 = acc[i][j][half * 2 + 1];
                if (EPI == 1) {
                    float2 old = *(const float2*)cp;
                    v0 += old.x; v1 += old.y;
                }
                *(float2*)cp = make_float2(v0, v1);
            }
        }
    }
}

constexpr int kSmem128 = 3 * (128 * 40 + 2 * 128 * 40) * 2;  // 92160
constexpr int kSmem64  = 3 * (64 * 40 + 2 * 128 * 40) * 2;   // 76800

// =====================================================================
// fp32 GEMM (dt_proj, K=48)
// =====================================================================
template <int EPI, int BMt>
__global__ __launch_bounds__(256)
void sgemm_tn_kernel(const float* __restrict__ A, int lda,
                     const float* __restrict__ Bw,
                     float* __restrict__ C, int ldc,
                     const float* __restrict__ bias,
                     int M, int N, int K) {
    constexpr int BN = 128, BK = 8;
    constexpr int MR = BMt / 16;
    constexpr int AE = BMt * BK / 256;
    __shared__ float As[2][BK][BMt + 4];
    __shared__ float Bs[2][BK][BN + 4];

    const int tid = threadIdx.x;
    const int bm0 = blockIdx.y * BMt;
    const int bn0 = blockIdx.x * BN;
    const int tx = tid & 15;
    const int ty = tid >> 4;

    const int blr = tid >> 1;
    const int bk4 = (tid & 1) * 4;
    const int gnb = bn0 + blr;
    const bool bvalid = (gnb < N);
    const float* Bbase = Bw + (size_t)gnb * K + bk4;

    float aR[AE];
    float4 bR;

#pragma unroll
    for (int u = 0; u < AE; u++) {
        int e = tid + u * 256;
        int r = e >> 3, k = e & 7;
        aR[u] = A[(size_t)(bm0 + r) * lda + k];
    }
    bR = bvalid ? *(const float4*)Bbase : make_float4(0.f, 0.f, 0.f, 0.f);
#pragma unroll
    for (int u = 0; u < AE; u++) {
        int e = tid + u * 256;
        As[0][e & 7][e >> 3] = aR[u];
    }
    Bs[0][bk4 + 0][blr] = bR.x;
    Bs[0][bk4 + 1][blr] = bR.y;
    Bs[0][bk4 + 2][blr] = bR.z;
    Bs[0][bk4 + 3][blr] = bR.w;
    __syncthreads();

    float acc[MR][8];
#pragma unroll
    for (int i = 0; i < MR; i++)
#pragma unroll
        for (int j = 0; j < 8; j++) acc[i][j] = 0.f;

    const int KT = K / BK;
    int buf = 0;
    for (int kt = 0; kt < KT; kt++) {
        if (kt + 1 < KT) {
            const int k0 = (kt + 1) * BK;
#pragma unroll
            for (int u = 0; u < AE; u++) {
                int e = tid + u * 256;
                int r = e >> 3, k = e & 7;
                aR[u] = A[(size_t)(bm0 + r) * lda + k0 + k];
            }
            bR = bvalid ? *(const float4*)(Bbase + k0) : make_float4(0.f, 0.f, 0.f, 0.f);
        }
#pragma unroll
        for (int k = 0; k < BK; k++) {
            float a[MR], b[8];
            {
                float4 a0 = *(const float4*)&As[buf][k][ty * 4];
                a[0] = a0.x; a[1] = a0.y; a[2] = a0.z; a[3] = a0.w;
                if (MR == 8) {
                    float4 a1 = *(const float4*)&As[buf][k][ty * 4 + 64];
                    a[4] = a1.x; a[5] = a1.y; a[6] = a1.z; a[7] = a1.w;
                }
                float4 b0 = *(const float4*)&Bs[buf][k][tx * 4];
                float4 b1 = *(const float4*)&Bs[buf][k][tx * 4 + 64];
                b[0] = b0.x; b[1] = b0.y; b[2] = b0.z; b[3] = b0.w;
                b[4] = b1.x; b[5] = b1.y; b[6] = b1.z; b[7] = b1.w;
            }
#pragma unroll
            for (int i = 0; i < MR; i++)
#pragma unroll
                for (int j = 0; j < 8; j++)
                    acc[i][j] = fmaf(a[i], b[j], acc[i][j]);
        }
        if (kt + 1 < KT) {
            int nb = buf ^ 1;
#pragma unroll
            for (int u = 0; u < AE; u++) {
                int e = tid + u * 256;
                As[nb][e & 7][e >> 3] = aR[u];
            }
            Bs[nb][bk4 + 0][blr] = bR.x;
            Bs[nb][bk4 + 1][blr] = bR.y;
            Bs[nb][bk4 + 2][blr] = bR.z;
            Bs[nb][bk4 + 3][blr] = bR.w;
            __syncthreads();
            buf = nb;
        }
    }

#pragma unroll
    for (int i = 0; i < MR; i++) {
        int gm = bm0 + ty * 4 + (i & 3) + (i >> 2) * 64;
#pragma unroll
        for (int jj = 0; jj < 2; jj++) {
            int gn = bn0 + tx * 4 + jj * 64;
            if (gn >= N) continue;
            float v0 = acc[i][jj * 4 + 0];
            float v1 = acc[i][jj * 4 + 1];
            float v2 = acc[i][jj * 4 + 2];
            float v3 = acc[i][jj * 4 + 3];
            float* cp = C + (size_t)gm * ldc + gn;
            if (EPI == 1) {
                float4 old = *(const float4*)cp;
                v0 += old.x; v1 += old.y; v2 += old.z; v3 += old.w;
            }
            if (EPI == 2) {
                float bb[4] = {bias[gn], bias[gn + 1], bias[gn + 2], bias[gn + 3]};
                v0 += bb[0]; v1 += bb[1]; v2 += bb[2]; v3 += bb[3];
                v0 = fmaxf(v0, 0.f) + log1pf(expf(-fabsf(v0)));
                v1 = fmaxf(v1, 0.f) + log1pf(expf(-fabsf(v1)));
                v2 = fmaxf(v2, 0.f) + log1pf(expf(-fabsf(v2)));
                v3 = fmaxf(v3, 0.f) + log1pf(expf(-fabsf(v3)));
            }
            *(float4*)cp = make_float4(v0, v1, v2, v3);
        }
    }
}

// =====================================================================
// x_proj split-K GEMM + reduce
// =====================================================================
__global__ void gemm_xproj_splitk(const float* __restrict__ A,
                                  const float* __restrict__ Bw,
                                  float* __restrict__ part) {
    constexpr int BM = 64, BN = 64, BK = 16;
    __shared__ float As[BK][BM + 4];
    __shared__ float Bs[BK][BN + 4];
    const int tid = threadIdx.x;
    const int bm0 = blockIdx.y * BM;
    const int bn0 = blockIdx.x * BN;
    const int zoff = blockIdx.z * kXPKC;
    const int tx = tid & 15;
    const int ty = tid >> 4;
    float acc[4][4] = {};

    for (int k0 = 0; k0 < kXPKC; k0 += BK) {
#pragma unroll
        for (int t = tid; t < BM * BK; t += 256) {
            int m = t >> 4, k = t & 15;
            As[k][m] = A[(size_t)(bm0 + m) * kDI + zoff + k0 + k];
        }
#pragma unroll
        for (int t = tid; t < BN * BK; t += 256) {
            int n = t >> 4, k = t & 15;
            int gn = bn0 + n;
            Bs[k][n] = (gn < kDBC) ? Bw[(size_t)gn * kDI + zoff + k0 + k] : 0.f;
        }
        __syncthreads();
#pragma unroll
        for (int k = 0; k < BK; k++) {
            float a[4], b[4];
#pragma unroll
            for (int i = 0; i < 4; i++) a[i] = As[k][ty * 4 + i];
#pragma unroll
            for (int j = 0; j < 4; j++) b[j] = Bs[k][tx * 4 + j];
#pragma unroll
            for (int i = 0; i < 4; i++)
#pragma unroll
                for (int j = 0; j < 4; j++)
                    acc[i][j] = fmaf(a[i], b[j], acc[i][j]);
        }
        __syncthreads();
    }

    float* base = part + (size_t)blockIdx.z * kRows * kDBC;
#pragma unroll
    for (int i = 0; i < 4; i++) {
        int gm = bm0 + ty * 4 + i;
#pragma unroll
        for (int j = 0; j < 4; j++) {
            int gn = bn0 + tx * 4 + j;
            if (gn < kDBC) base[(size_t)gm * kDBC + gn] = acc[i][j];
        }
    }
}

__global__ void reduce_dbc_kernel(const float* __restrict__ part,
                                  float* __restrict__ dbc) {
    int idx = blockIdx.x * blockDim.x + threadIdx.x;
    if (idx >= kRows * kDBC) return;
    float s = 0.f;
#pragma unroll
    for (int z = 0; z < kXPChunks; z++)
        s += part[(size_t)z * kRows * kDBC + idx];
    dbc[idx] = s;
}

// ---------------- causal depthwise conv (DC=4) + SiLU, float4 ----------------
__global__ void conv_silu_kernel(const float* __restrict__ xz,
                                 const float* __restrict__ cw,
                                 const float* __restrict__ cb,
                                 float* __restrict__ xc) {
    int idx = blockIdx.x * blockDim.x + threadIdx.x;   // float4 index
    int total = kRows * kDI / 4;
    if (idx >= total) return;
    int i4 = idx % (kDI / 4);
    int r = idx / (kDI / 4);
    int l = r % kL;
    int b = r / kL;
    int i = i4 * 4;

    float4 acc = *(const float4*)(cb + i);
#pragma unroll
    for (int k = 0; k < kDC; k++) {
        int ls = l + k - (kDC - 1);
        if (ls >= 0) {
            const float4 xv = *(const float4*)(xz + ((size_t)(b * kL + ls)) * (2 * kDI) + i);
            acc.x = fmaf(xv.x, cw[(i + 0) * kDC + k], acc.x);
            acc.y = fmaf(xv.y, cw[(i + 1) * kDC + k], acc.y);
            acc.z = fmaf(xv.z, cw[(i + 2) * kDC + k], acc.z);
            acc.w = fmaf(xv.w, cw[(i + 3) * kDC + k], acc.w);
        }
    }
    acc.x = acc.x / (1.f + __expf(-acc.x));
    acc.y = acc.y / (1.f + __expf(-acc.y));
    acc.z = acc.z / (1.f + __expf(-acc.z));
    acc.w = acc.w / (1.f + __expf(-acc.w));
    *(float4*)(xc + (size_t)r * kDI + i) = acc;
}

// =====================================================================
// chunked selective scan (3 passes)
// =====================================================================
__global__ __launch_bounds__(256)
void scan_p1(const float* __restrict__ dt,
             const float* __restrict__ xc,
             const float* __restrict__ dbc,
             const float* __restrict__ A_log,
             float* __restrict__ E, float* __restrict__ U) {
    int t = blockIdx.x * 256 + threadIdx.x;
    int s = t & 15;
    int rest = t >> 4;
    int i = rest % kDI;
    int bc = rest / kDI;
    int c = bc & (kNCH - 1);
    int b = bc >> 5;

    const float a = -__expf(A_log[i * kDS + s]);
    float h = 0.f, Ep = 1.f;
    size_t r0 = (size_t)b * kL + c * kG;
    const float* pdt = dt + r0 * kDI + i;
    const float* pxc = xc + r0 * kDI + i;
    const float* pB  = dbc + r0 * kDBC + kDTR + s;
#pragma unroll 4
    for (int g = 0; g < kG; g++) {
        float dt_t = *pdt, x_t = *pxc, Bt = *pB;
        float e = __expf(dt_t * a);
        h = fmaf(h, e, dt_t * x_t * Bt);
        Ep *= e;
        pdt += kDI; pxc += kDI; pB += kDBC;
    }
    E[t] = Ep;
    U[t] = h;
}

__global__ __launch_bounds__(256)
void scan_p2(const float* __restrict__ E,
             const float* __restrict__ U,
             float* __restrict__ H) {
    int t = blockIdx.x * 256 + threadIdx.x;
    int sb = t >> 4;
    int s = t & 15;
    int i = sb % kDI;
    int b = sb / kDI;
    float h = 0.f;
#pragma unroll
    for (int c = 0; c < kNCH; c++) {
        size_t idx = ((((size_t)b * kNCH + c) * kDI + i) << 4) + s;
        H[idx] = h;
        h = fmaf(E[idx], h, U[idx]);
    }
}

__global__ __launch_bounds__(256)
void scan_p3(const float* __restrict__ dt,
             const float* __restrict__ xc,
             const float* __restrict__ dbc,
             const float* __restrict__ xz,
             const float* __restrict__ A_log,
             const float* __restrict__ D_skip,
             const float* __restrict__ H,
             __nv_bfloat16* __restrict__ yh) {
    int t = blockIdx.x * 256 + threadIdx.x;
    int s = t & 15;
    int rest = t >> 4;
    int i = rest % kDI;
    int bc = rest / kDI;
    int c = bc & (kNCH - 1);
    int b = bc >> 5;

    const float a = -__expf(A_log[i * kDS + s]);
    const float dsk = D_skip[i];
    float h = H[t];
    size_t r0 = (size_t)b * kL + c * kG;
    const float* pdt = dt + r0 * kDI + i;
    const float* pxc = xc + r0 * kDI + i;
    const float* pB  = dbc + r0 * kDBC + kDTR + s;
    const float* pC  = dbc + r0 * kDBC + kDTR + kDS + s;
    const float* pz  = xz + r0 * (2 * kDI) + kDI + i;
    __nv_bfloat16* pyh = yh + r0 * kDI + i;
#pragma unroll 4
    for (int g = 0; g < kG; g++) {
        float dt_t = *pdt, x_t = *pxc, Bt = *pB, Ct = *pC;
        float e = __expf(dt_t * a);
        h = fmaf(h, e, dt_t * x_t * Bt);
        float p = h * Ct;
        p += __shfl_xor_sync(0xffffffffu, p, 8);
        p += __shfl_xor_sync(0xffffffffu, p, 4);
        p += __shfl_xor_sync(0xffffffffu, p, 2);
        p += __shfl_xor_sync(0xffffffffu, p, 1);
        if (s == 0) {
            float z = *pz;
            float yy = fmaf(x_t, dsk, p);
            yy *= z / (1.f + __expf(-z));
            *pyh = __float2bfloat16_rn(yy);
        }
        pdt += kDI; pxc += kDI; pB += kDBC; pC += kDBC;
        pz += 2 * kDI; pyh += kDI;
    }
}

// ---------------- final head ----------------
__global__ void head_kernel(const float* __restrict__ xn,
                            const float* __restrict__ cls_w,
                            const float* __restrict__ cls_b,
                            float* __restrict__ out) {
    int b = blockIdx.x;
    __shared__ float mean[kD];
    for (int d = threadIdx.x; d < kD; d += blockDim.x) {
        float s = 0.f;
        const float* p = xn + ((size_t)b * kL) * kD + d;
        for (int l = 0; l < kL; l++) s += p[(size_t)l * kD];
        mean[d] = s / (float)kL;
    }
    __syncthreads();
    if (threadIdx.x < kNC) {
        int c = threadIdx.x;
        float s = cls_b[c];
        for (int d = 0; d < kD; d++) s = fmaf(mean[d], cls_w[c * kD + d], s);
        out[b * kNC + c] = s;
    }
}

// ---------------- launch ----------------
extern "C" void kernel_launch(void* const* d_in, const int* in_sizes, int n_in,
                              void* d_out, int out_size) {
    const int*   input_ids = (const int*)  d_in[0];
    const float* embed     = (const float*)d_in[1];
    const float* norm_w    = (const float*)d_in[2];
    const float* in_proj_w = (const float*)d_in[3];
    const float* conv_w    = (const float*)d_in[4];
    const float* conv_b    = (const float*)d_in[5];
    const float* x_proj_w  = (const float*)d_in[6];
    const float* dt_proj_w = (const float*)d_in[7];
    const float* dt_proj_b = (const float*)d_in[8];
    const float* A_log     = (const float*)d_in[9];
    const float* D_skip    = (const float*)d_in[10];
    const float* out_proj_w= (const float*)d_in[11];
    const float* norm_f_w  = (const float*)d_in[12];
    const float* cls_w     = (const float*)d_in[13];
    const float* cls_b     = (const float*)d_in[14];
    float* out = (float*)d_out;

    float *px, *pxn, *pxz, *pxc, *pdbc, *pdbp, *pdt, *pE, *pU, *pH;
    __nv_bfloat16 *pwinh, *pwinl, *pwouth, *pwoutl, *pxnh, *pyh;
    cudaGetSymbolAddress((void**)&px,    g_x);
    cudaGetSymbolAddress((void**)&pxn,   g_xn);
    cudaGetSymbolAddress((void**)&pxz,   g_xz);
    cudaGetSymbolAddress((void**)&pxc,   g_xc);
    cudaGetSymbolAddress((void**)&pdbc,  g_dbc);
    cudaGetSymbolAddress((void**)&pdbp,  g_dbp);
    cudaGetSymbolAddress((void**)&pdt,   g_dt);
    cudaGetSymbolAddress((void**)&pE,    g_E);
    cudaGetSymbolAddress((void**)&pU,    g_U);
    cudaGetSymbolAddress((void**)&pH,    g_H);
    cudaGetSymbolAddress((void**)&pwinh, g_winh);
    cudaGetSymbolAddress((void**)&pwinl, g_winl);
    cudaGetSymbolAddress((void**)&pwouth,g_wouth);
    cudaGetSymbolAddress((void**)&pwoutl,g_woutl);
    cudaGetSymbolAddress((void**)&pxnh,  g_xnh);
    cudaGetSymbolAddress((void**)&pyh,   g_yh);

    cudaFuncSetAttribute(hgemm_ps_kernel<0, 128>,
                         cudaFuncAttributeMaxDynamicSharedMemorySize, kSmem128);
    cudaFuncSetAttribute(hgemm_ps_kernel<1, 64>,
                         cudaFuncAttributeMaxDynamicSharedMemorySize, kSmem64);

    const int scanBlocks = kScanN / 256;          // 6144
    const int p2Blocks = (kB * kDI * kDS) / 256;  // 192

    // launch 0: embed, 1: split_in, 2: rmsnorm(L0), 3: in_proj <- ncu capture
    {
        int total = kRows * kD / 4;
        embed_kernel<<<(total + 255) / 256, 256>>>(input_ids, embed, px);
    }
    {
        int n4 = kInWN / 4;
        split_f32_kernel<<<(n4 + 255) / 256, 256>>>(in_proj_w, pwinh, pwinl, n4);
    }

    for (int l = 0; l < kNL; l++) {
        const float* w_norm = norm_w    + (size_t)l * kD;
        const float* w_cw   = conv_w    + (size_t)l * kDI * kDC;
        const float* w_cb   = conv_b    + (size_t)l * kDI;
        const float* w_xp   = x_proj_w  + (size_t)l * kDBC * kDI;
        const float* w_dtw  = dt_proj_w + (size_t)l * kDI * kDTR;
        const float* w_dtb  = dt_proj_b + (size_t)l * kDI;
        const float* w_Al   = A_log     + (size_t)l * kDI * kDS;
        const float* w_Dsk  = D_skip    + (size_t)l * kDI;
        const __nv_bfloat16* w_inh  = pwinh  + (size_t)l * 2 * kDI * kD;
        const __nv_bfloat16* w_inl  = pwinl  + (size_t)l * 2 * kDI * kD;
        const __nv_bfloat16* w_outh = pwouth + (size_t)l * kD * kDI;
        const __nv_bfloat16* w_outl = pwoutl + (size_t)l * kD * kDI;

        // rmsnorm -> bf16 hi plane
        rmsnorm_kernel<true><<<kRows, 256>>>(px, w_norm, nullptr, pxnh);

        // in_proj: pre-split 2-term, 128x128 tiles, 3-stage pipeline
        {
            dim3 grid(2 * kDI / 128, kRows / 128);   // (24,16)
            hgemm_ps_kernel<0, 128><<<grid, 256, kSmem128>>>(
                pxnh, w_inh, w_inl, pxz, 2 * kDI, kD);
        }

        // conv + silu (float4)
        {
            int total = kRows * kDI / 4;
            conv_silu_kernel<<<(total + 255) / 256, 256>>>(pxz, w_cw, w_cb, pxc);
        }

        // x_proj split-K
        {
            dim3 grid(2, kRows / 64, kXPChunks);
            gemm_xproj_splitk<<<grid, 256>>>(pxc, w_xp, pdbp);
            int total = kRows * kDBC;
            reduce_dbc_kernel<<<(total + 255) / 256, 256>>>(pdbp, pdbc);
        }

        // dt (fp32, K=48)
        {
            dim3 grid(kDI / 128, kRows / 128);
            sgemm_tn_kernel<2, 128><<<grid, 256>>>(pdbc, kDBC, w_dtw, pdt, kDI,
                                                   w_dtb, kRows, kDI, kDTR);
        }

        // chunked selective scan
        scan_p1<<<scanBlocks, 256>>>(pdt, pxc, pdbc, w_Al, pE, pU);
        scan_p2<<<p2Blocks, 256>>>(pE, pU, pH);
        scan_p3<<<scanBlocks, 256>>>(pdt, pxc, pdbc, pxz, w_Al, w_Dsk, pH, pyh);

        // split out_proj weights once, before first use
        if (l == 0) {
            int n4 = kOutWN / 4;
            split_f32_kernel<<<(n4 + 255) / 256, 256>>>(out_proj_w, pwouth, pwoutl, n4);
        }

        // out_proj + residual: pre-split 2-term, 64x128 tiles, 3-stage pipeline
        {
            dim3 grid(kD / 128, kRows / 64);         // (6,32)
            hgemm_ps_kernel<1, 64><<<grid, 256, kSmem64>>>(
                pyh, w_outh, w_outl, px, kD, kDI);
        }
    }

    rmsnorm_kernel<false><<<kRows, 256>>>(px, norm_f_w, pxn, nullptr);
    head_kernel<<<kB, 256>>>(pxn, cls_w, cls_b, out);
}

// round 14
// speedup vs baseline: 1.3332x; 1.3332x over previous
#include <cuda_runtime.h>
#include <cuda_bf16.h>
#include <math.h>
#include <stdint.h>

// ---------------- problem constants ----------------
constexpr int kV   = 50280;
constexpr int kD   = 768;
constexpr int kNL  = 8;
constexpr int kDI  = 1536;
constexpr int kDS  = 16;
constexpr int kDC  = 4;
constexpr int kDTR = 48;
constexpr int kNC  = 4;
constexpr int kB   = 2;
constexpr int kL   = 1024;
constexpr int kDBC = kDTR + 2 * kDS;  // 80
constexpr float kEPS = 1e-5f;

constexpr int kRows = kB * kL;        // 2048
constexpr int kXPChunks = 8;
constexpr int kXPKC = kDI / kXPChunks; // 192

// chunked scan
constexpr int kG   = 32;
constexpr int kNCH = kL / kG;         // 32
constexpr int kScanN = kB * kNCH * kDI * kDS;   // 1.57M
constexpr int kScanT = kB * kNCH * kDI;         // 98304 threads (16 states each)

constexpr int kInWN  = kNL * 2 * kDI * kD;   // 18.9M
constexpr int kOutWN = kNL * kD * kDI;       // 9.4M

// ---------------- device scratch ----------------
__device__ float g_x  [kRows * kD];
__device__ float g_xn [kRows * kD];          // fp32 (final norm only)
__device__ float g_xz [kRows * 2 * kDI];
__device__ float g_xc [kRows * kDI];
__device__ float g_dbc[kRows * kDBC];
__device__ float g_dbp[kXPChunks * kRows * kDBC];
__device__ float g_dt [kRows * kDI];
__device__ float g_E  [kScanN];
__device__ float g_U  [kScanN];
__device__ float g_H  [kScanN];

__device__ __align__(16) __nv_bfloat16 g_winh[kInWN];
__device__ __align__(16) __nv_bfloat16 g_winl[kInWN];
__device__ __align__(16) __nv_bfloat16 g_wouth[kOutWN];
__device__ __align__(16) __nv_bfloat16 g_woutl[kOutWN];
__device__ __align__(16) __nv_bfloat16 g_xnh[kRows * kD];
__device__ __align__(16) __nv_bfloat16 g_yh [kRows * kDI];

// ---------------- helpers ----------------
__device__ __forceinline__ float warp_sum(float v) {
#pragma unroll
    for (int o = 16; o > 0; o >>= 1) v += __shfl_xor_sync(0xffffffffu, v, o);
    return v;
}
__device__ __forceinline__ uint32_t smem_u32(const void* p) {
    return (uint32_t)__cvta_generic_to_shared(p);
}
__device__ __forceinline__ void ldmat_x4(uint32_t& r0, uint32_t& r1,
                                         uint32_t& r2, uint32_t& r3,
                                         uint32_t addr) {
    asm volatile("ldmatrix.sync.aligned.m8n8.x4.shared.b16 {%0,%1,%2,%3}, [%4];"
                 : "=r"(r0), "=r"(r1), "=r"(r2), "=r"(r3) : "r"(addr));
}
__device__ __forceinline__ void mma16816(float* c, const uint32_t* a,
                                         uint32_t b0, uint32_t b1) {
    asm volatile(
        "mma.sync.aligned.m16n8k16.row.col.f32.bf16.bf16.f32 "
        "{%0,%1,%2,%3}, {%4,%5,%6,%7}, {%8,%9}, {%0,%1,%2,%3};"
        : "+f"(c[0]), "+f"(c[1]), "+f"(c[2]), "+f"(c[3])
        : "r"(a[0]), "r"(a[1]), "r"(a[2]), "r"(a[3]), "r"(b0), "r"(b1));
}
__device__ __forceinline__ void cp16(uint32_t dst, const void* src) {
    asm volatile("cp.async.cg.shared.global [%0], [%1], 16;\n" :: "r"(dst), "l"(src));
}
__device__ __forceinline__ void cp_commit() {
    asm volatile("cp.async.commit_group;\n");
}
template <int N>
__device__ __forceinline__ void cp_wait() {
    asm volatile("cp.async.wait_group %0;\n" :: "n"(N));
}

// ---------------- weight hi/lo split ----------------
__global__ void split_f32_kernel(const float* __restrict__ src,
                                 __nv_bfloat16* __restrict__ h,
                                 __nv_bfloat16* __restrict__ l, int n4) {
    int i = blockIdx.x * blockDim.x + threadIdx.x;
    if (i >= n4) return;
    float4 v = ((const float4*)src)[i];
    __nv_bfloat162 h01 = __floats2bfloat162_rn(v.x, v.y);
    __nv_bfloat162 h23 = __floats2bfloat162_rn(v.z, v.w);
    __nv_bfloat162 l01 = __floats2bfloat162_rn(v.x - __bfloat162float(h01.x),
                                               v.y - __bfloat162float(h01.y));
    __nv_bfloat162 l23 = __floats2bfloat162_rn(v.z - __bfloat162float(h23.x),
                                               v.w - __bfloat162float(h23.y));
    ((__nv_bfloat162*)h)[i * 2]     = h01;
    ((__nv_bfloat162*)h)[i * 2 + 1] = h23;
    ((__nv_bfloat162*)l)[i * 2]     = l01;
    ((__nv_bfloat162*)l)[i * 2 + 1] = l23;
}

// ---------------- embed gather ----------------
__global__ void embed_kernel(const int* __restrict__ ids,
                             const float* __restrict__ embed,
                             float* __restrict__ x) {
    int idx = blockIdx.x * blockDim.x + threadIdx.x;
    int total = kRows * kD / 4;
    if (idx >= total) return;
    int row = idx / (kD / 4);
    int d4 = idx - row * (kD / 4);
    const float4* src = (const float4*)(embed + (size_t)ids[row] * kD);
    ((float4*)x)[idx] = src[d4];
}

// ---------------- rmsnorm: SPLIT -> bf16 hi plane; else fp32 ----------------
template <bool SPLIT>
__global__ void rmsnorm_kernel(const float* __restrict__ x,
                               const float* __restrict__ w,
                               float* __restrict__ outf,
                               __nv_bfloat16* __restrict__ outh) {
    int row = blockIdx.x;
    const float* xr = x + (size_t)row * kD;
    float s = 0.f;
    for (int d = threadIdx.x; d < kD; d += blockDim.x) {
        float v = xr[d];
        s = fmaf(v, v, s);
    }
    s = warp_sum(s);
    __shared__ float sh[8];
    __shared__ float inv_s;
    int wid = threadIdx.x >> 5, lane = threadIdx.x & 31;
    if (lane == 0) sh[wid] = s;
    __syncthreads();
    if (wid == 0) {
        float t = (lane < (blockDim.x >> 5)) ? sh[lane] : 0.f;
        t = warp_sum(t);
        if (lane == 0) inv_s = rsqrtf(t / (float)kD + kEPS);
    }
    __syncthreads();
    float inv = inv_s;
    for (int d = threadIdx.x; d < kD; d += blockDim.x) {
        float v = xr[d] * inv * w[d];
        if (SPLIT) outh[(size_t)row * kD + d] = __float2bfloat16_rn(v);
        else       outf[(size_t)row * kD + d] = v;
    }
}

// =====================================================================
// Pre-split bf16 tensor-core GEMM, 3-stage cp.async, single sync/kt.
//   C[M,N] = Ah[M,K] @ (Bh + Bl)[N,K]^T    (round-10/12 numerics)
//   BM in {64,128}, BN=128, BK=32, 256 threads (8 warps: 2 in M, 4 in N)
// EPI 0: store    EPI 1: C += result
// =====================================================================
template <int EPI, int BM>
__global__ __launch_bounds__(256, 2)
void hgemm_ps_kernel(const __nv_bfloat16* __restrict__ Ah,
                     const __nv_bfloat16* __restrict__ Bh,
                     const __nv_bfloat16* __restrict__ Bl,
                     float* __restrict__ C, int ldc, int K) {
    constexpr int BN = 128, BK = 32;
    constexpr int STR = 40;
    constexpr int WM = BM / 2;
    constexpr int MF = WM / 16;
    constexpr int ASZ = BM * STR;
    constexpr int BSZ = BN * STR;
    constexpr int ACH = BM / 64;        // A cp16 per thread (1 or 2)
    constexpr int ST = 3;               // pipeline stages

    extern __shared__ __nv_bfloat16 sm[];
    __nv_bfloat16* As_h = sm;                    // [ST][ASZ]
    __nv_bfloat16* Bs_h = As_h + ST * ASZ;       // [ST][BSZ]
    __nv_bfloat16* Bs_l = Bs_h + ST * BSZ;       // [ST][BSZ]

    const int tid = threadIdx.x;
    const int wid = tid >> 5, lane = tid & 31;
    const int bm0 = blockIdx.y * BM;
    const int bn0 = blockIdx.x * BN;
    const int wm = wid & 1;
    const int wn = wid >> 1;

    float acc[MF][4][4];
#pragma unroll
    for (int i = 0; i < MF; i++)
#pragma unroll
        for (int j = 0; j < 4; j++)
#pragma unroll
            for (int v = 0; v < 4; v++) acc[i][j][v] = 0.f;

    auto issue_loads = [&](int buf, int k0) {
#pragma unroll
        for (int u = 0; u < ACH; u++) {
            int id = tid + u * 256;
            int r = id >> 2, c8 = (id & 3) * 8;
            size_t g = (size_t)(bm0 + r) * K + k0 + c8;
            cp16(smem_u32(As_h + buf * ASZ + r * STR + c8), Ah + g);
        }
#pragma unroll
        for (int u = 0; u < 2; u++) {
            int id = tid + u * 256;
            int r = id >> 2, c8 = (id & 3) * 8;
            size_t g = (size_t)(bn0 + r) * K + k0 + c8;
            uint32_t soff = (uint32_t)(buf * BSZ + r * STR + c8);
            cp16(smem_u32(Bs_h + soff), Bh + g);
            cp16(smem_u32(Bs_l + soff), Bl + g);
        }
    };

    const int a_row = wm * WM + (lane & 15);
    const int a_col8 = (lane >> 4) << 3;
    const int b_grp = lane >> 3;
    const int b_row = wn * 32 + ((b_grp >> 1) << 3) + (lane & 7);
    const int b_col8 = (b_grp & 1) << 3;

    const int KT = K / BK;
    issue_loads(0, 0);
    cp_commit();
    if (KT > 1) { issue_loads(1, BK); cp_commit(); }

    for (int kt = 0; kt < KT; kt++) {
        if (kt + 1 < KT) cp_wait<1>(); else cp_wait<0>();
        __syncthreads();
        if (kt + 2 < KT) {
            issue_loads((kt + 2) % ST, (kt + 2) * BK);
            cp_commit();
        }
        const int buf = kt % ST;

#pragma unroll
        for (int kk = 0; kk < 2; kk++) {
            uint32_t ah[MF][4];
            uint32_t bh[4][2], bl[4][2];
#pragma unroll
            for (int i = 0; i < MF; i++) {
                uint32_t off = (uint32_t)(buf * ASZ + (a_row + i * 16) * STR
                                          + kk * 16 + a_col8);
                ldmat_x4(ah[i][0], ah[i][1], ah[i][2], ah[i][3],
                         smem_u32(As_h + off));
            }
#pragma unroll
            for (int jj = 0; jj < 2; jj++) {
                uint32_t off = (uint32_t)(buf * BSZ + (b_row + jj * 16) * STR
                                          + kk * 16 + b_col8);
                ldmat_x4(bh[jj * 2][0], bh[jj * 2][1],
                         bh[jj * 2 + 1][0], bh[jj * 2 + 1][1],
                         smem_u32(Bs_h + off));
                ldmat_x4(bl[jj * 2][0], bl[jj * 2][1],
                         bl[jj * 2 + 1][0], bl[jj * 2 + 1][1],
                         smem_u32(Bs_l + off));
            }
#pragma unroll
            for (int i = 0; i < MF; i++)
#pragma unroll
                for (int j = 0; j < 4; j++) {
                    mma16816(acc[i][j], ah[i], bh[j][0], bh[j][1]);
                    mma16816(acc[i][j], ah[i], bl[j][0], bl[j][1]);
                }
        }
    }

    const int c_row = bm0 + wm * WM + (lane >> 2);
    const int c_col = bn0 + wn * 32 + (lane & 3) * 2;
#pragma unroll
    for (int i = 0; i < MF; i++) {
#pragma unroll
        for (int j = 0; j < 4; j++) {
#pragma unroll
            for (int half = 0; half < 2; half++) {
                int gm = c_row + i * 16 + half * 8;
                int gn = c_col + j * 8;
                float* cp = C + (size_t)gm * ldc + gn;
                float v0 = acc[i][j][half * 2 + 0];
                float v1 = acc[i][j][half * 2 + 1];
                if (EPI == 1) {
                    float2 old = *(const float2*)cp;
                    v0 += old.x; v1 += old.y;
                }
                *(float2*)cp = make_float2(v0, v1);
            }
        }
    }
}

constexpr int kSmem128 = 3 * (128 * 40 + 2 * 128 * 40) * 2;  // 92160
constexpr int kSmem64  = 3 * (64 * 40 + 2 * 128 * 40) * 2;   // 76800

// =====================================================================
// fp32 GEMM (dt_proj, K=48)
// =====================================================================
template <int EPI, int BMt>
__global__ __launch_bounds__(256)
void sgemm_tn_kernel(const float* __restrict__ A, int lda,
                     const float* __restrict__ Bw,
                     float* __restrict__ C, int ldc,
                     const float* __restrict__ bias,
                     int M, int N, int K) {
    constexpr int BN = 128, BK = 8;
    constexpr int MR = BMt / 16;
    constexpr int AE = BMt * BK / 256;
    __shared__ float As[2][BK][BMt + 4];
    __shared__ float Bs[2][BK][BN + 4];

    const int tid = threadIdx.x;
    const int bm0 = blockIdx.y * BMt;
    const int bn0 = blockIdx.x * BN;
    const int tx = tid & 15;
    const int ty = tid >> 4;

    const int blr = tid >> 1;
    const int bk4 = (tid & 1) * 4;
    const int gnb = bn0 + blr;
    const bool bvalid = (gnb < N);
    const float* Bbase = Bw + (size_t)gnb * K + bk4;

    float aR[AE];
    float4 bR;

#pragma unroll
    for (int u = 0; u < AE; u++) {
        int e = tid + u * 256;
        int r = e >> 3, k = e & 7;
        aR[u] = A[(size_t)(bm0 + r) * lda + k];
    }
    bR = bvalid ? *(const float4*)Bbase : make_float4(0.f, 0.f, 0.f, 0.f);
#pragma unroll
    for (int u = 0; u < AE; u++) {
        int e = tid + u * 256;
        As[0][e & 7][e >> 3] = aR[u];
    }
    Bs[0][bk4 + 0][blr] = bR.x;
    Bs[0][bk4 + 1][blr] = bR.y;
    Bs[0][bk4 + 2][blr] = bR.z;
    Bs[0][bk4 + 3][blr] = bR.w;
    __syncthreads();

    float acc[MR][8];
#pragma unroll
    for (int i = 0; i < MR; i++)
#pragma unroll
        for (int j = 0; j < 8; j++) acc[i][j] = 0.f;

    const int KT = K / BK;
    int buf = 0;
    for (int kt = 0; kt < KT; kt++) {
        if (kt + 1 < KT) {
            const int k0 = (kt + 1) * BK;
#pragma unroll
            for (int u = 0; u < AE; u++) {
                int e = tid + u * 256;
                int r = e >> 3, k = e & 7;
                aR[u] = A[(size_t)(bm0 + r) * lda + k0 + k];
            }
            bR = bvalid ? *(const float4*)(Bbase + k0) : make_float4(0.f, 0.f, 0.f, 0.f);
        }
#pragma unroll
        for (int k = 0; k < BK; k++) {
            float a[MR], b[8];
            {
                float4 a0 = *(const float4*)&As[buf][k][ty * 4];
                a[0] = a0.x; a[1] = a0.y; a[2] = a0.z; a[3] = a0.w;
                if (MR == 8) {
                    float4 a1 = *(const float4*)&As[buf][k][ty * 4 + 64];
                    a[4] = a1.x; a[5] = a1.y; a[6] = a1.z; a[7] = a1.w;
                }
                float4 b0 = *(const float4*)&Bs[buf][k][tx * 4];
                float4 b1 = *(const float4*)&Bs[buf][k][tx * 4 + 64];
                b[0] = b0.x; b[1] = b0.y; b[2] = b0.z; b[3] = b0.w;
                b[4] = b1.x; b[5] = b1.y; b[6] = b1.z; b[7] = b1.w;
            }
#pragma unroll
            for (int i = 0; i < MR; i++)
#pragma unroll
                for (int j = 0; j < 8; j++)
                    acc[i][j] = fmaf(a[i], b[j], acc[i][j]);
        }
        if (kt + 1 < KT) {
            int nb = buf ^ 1;
#pragma unroll
            for (int u = 0; u < AE; u++) {
                int e = tid + u * 256;
                As[nb][e & 7][e >> 3] = aR[u];
            }
            Bs[nb][bk4 + 0][blr] = bR.x;
            Bs[nb][bk4 + 1][blr] = bR.y;
            Bs[nb][bk4 + 2][blr] = bR.z;
            Bs[nb][bk4 + 3][blr] = bR.w;
            __syncthreads();
            buf = nb;
        }
    }

#pragma unroll
    for (int i = 0; i < MR; i++) {
        int gm = bm0 + ty * 4 + (i & 3) + (i >> 2) * 64;
#pragma unroll
        for (int jj = 0; jj < 2; jj++) {
            int gn = bn0 + tx * 4 + jj * 64;
            if (gn >= N) continue;
            float v0 = acc[i][jj * 4 + 0];
            float v1 = acc[i][jj * 4 + 1];
            float v2 = acc[i][jj * 4 + 2];
            float v3 = acc[i][jj * 4 + 3];
            float* cp = C + (size_t)gm * ldc + gn;
            if (EPI == 1) {
                float4 old = *(const float4*)cp;
                v0 += old.x; v1 += old.y; v2 += old.z; v3 += old.w;
            }
            if (EPI == 2) {
                float bb[4] = {bias[gn], bias[gn + 1], bias[gn + 2], bias[gn + 3]};
                v0 += bb[0]; v1 += bb[1]; v2 += bb[2]; v3 += bb[3];
                v0 = fmaxf(v0, 0.f) + log1pf(expf(-fabsf(v0)));
                v1 = fmaxf(v1, 0.f) + log1pf(expf(-fabsf(v1)));
                v2 = fmaxf(v2, 0.f) + log1pf(expf(-fabsf(v2)));
                v3 = fmaxf(v3, 0.f) + log1pf(expf(-fabsf(v3)));
            }
            *(float4*)cp = make_float4(v0, v1, v2, v3);
        }
    }
}

// =====================================================================
// x_proj split-K GEMM + reduce
// =====================================================================
__global__ void gemm_xproj_splitk(const float* __restrict__ A,
                                  const float* __restrict__ Bw,
                                  float* __restrict__ part) {
    constexpr int BM = 64, BN = 64, BK = 16;
    __shared__ float As[BK][BM + 4];
    __shared__ float Bs[BK][BN + 4];
    const int tid = threadIdx.x;
    const int bm0 = blockIdx.y * BM;
    const int bn0 = blockIdx.x * BN;
    const int zoff = blockIdx.z * kXPKC;
    const int tx = tid & 15;
    const int ty = tid >> 4;
    float acc[4][4] = {};

    for (int k0 = 0; k0 < kXPKC; k0 += BK) {
#pragma unroll
        for (int t = tid; t < BM * BK; t += 256) {
            int m = t >> 4, k = t & 15;
            As[k][m] = A[(size_t)(bm0 + m) * kDI + zoff + k0 + k];
        }
#pragma unroll
        for (int t = tid; t < BN * BK; t += 256) {
            int n = t >> 4, k = t & 15;
            int gn = bn0 + n;
            Bs[k][n] = (gn < kDBC) ? Bw[(size_t)gn * kDI + zoff + k0 + k] : 0.f;
        }
        __syncthreads();
#pragma unroll
        for (int k = 0; k < BK; k++) {
            float a[4], b[4];
#pragma unroll
            for (int i = 0; i < 4; i++) a[i] = As[k][ty * 4 + i];
#pragma unroll
            for (int j = 0; j < 4; j++) b[j] = Bs[k][tx * 4 + j];
#pragma unroll
            for (int i = 0; i < 4; i++)
#pragma unroll
                for (int j = 0; j < 4; j++)
                    acc[i][j] = fmaf(a[i], b[j], acc[i][j]);
        }
        __syncthreads();
    }

    float* base = part + (size_t)blockIdx.z * kRows * kDBC;
#pragma unroll
    for (int i = 0; i < 4; i++) {
        int gm = bm0 + ty * 4 + i;
#pragma unroll
        for (int j = 0; j < 4; j++) {
            int gn = bn0 + tx * 4 + j;
            if (gn < kDBC) base[(size_t)gm * kDBC + gn] = acc[i][j];
        }
    }
}

__global__ void reduce_dbc_kernel(const float* __restrict__ part,
                                  float* __restrict__ dbc) {
    int idx = blockIdx.x * blockDim.x + threadIdx.x;
    if (idx >= kRows * kDBC) return;
    float s = 0.f;
#pragma unroll
    for (int z = 0; z < kXPChunks; z++)
        s += part[(size_t)z * kRows * kDBC + idx];
    dbc[idx] = s;
}

// ---------------- causal depthwise conv (DC=4) + SiLU, float4 ----------------
__global__ void conv_silu_kernel(const float* __restrict__ xz,
                                 const float* __restrict__ cw,
                                 const float* __restrict__ cb,
                                 float* __restrict__ xc) {
    int idx = blockIdx.x * blockDim.x + threadIdx.x;
    int total = kRows * kDI / 4;
    if (idx >= total) return;
    int i4 = idx % (kDI / 4);
    int r = idx / (kDI / 4);
    int l = r % kL;
    int b = r / kL;
    int i = i4 * 4;

    float4 acc = *(const float4*)(cb + i);
#pragma unroll
    for (int k = 0; k < kDC; k++) {
        int ls = l + k - (kDC - 1);
        if (ls >= 0) {
            const float4 xv = *(const float4*)(xz + ((size_t)(b * kL + ls)) * (2 * kDI) + i);
            acc.x = fmaf(xv.x, cw[(i + 0) * kDC + k], acc.x);
            acc.y = fmaf(xv.y, cw[(i + 1) * kDC + k], acc.y);
            acc.z = fmaf(xv.z, cw[(i + 2) * kDC + k], acc.z);
            acc.w = fmaf(xv.w, cw[(i + 3) * kDC + k], acc.w);
        }
    }
    acc.x = acc.x / (1.f + __expf(-acc.x));
    acc.y = acc.y / (1.f + __expf(-acc.y));
    acc.z = acc.z / (1.f + __expf(-acc.z));
    acc.w = acc.w / (1.f + __expf(-acc.w));
    *(float4*)(xc + (size_t)r * kDI + i) = acc;
}

// =====================================================================
// chunked selective scan — register-state version
//   one thread per (b, chunk, i); all 16 states in registers.
//   n = (b*NCH + c)*DI + i;  E/U/H layout unchanged: idx = n*16 + s
// =====================================================================
__global__ __launch_bounds__(256)
void scan_p1(const float* __restrict__ dt,
             const float* __restrict__ xc,
             const float* __restrict__ dbc,
             const float* __restrict__ A_log,
             float* __restrict__ E, float* __restrict__ U) {
    int n = blockIdx.x * 256 + threadIdx.x;
    if (n >= kScanT) return;
    int i = n % kDI;
    int bc = n / kDI;
    int c = bc & (kNCH - 1);
    int b = bc >> 5;

    float a[kDS];
#pragma unroll
    for (int q = 0; q < 4; q++) {
        float4 v = *(const float4*)(A_log + (size_t)i * kDS + q * 4);
        a[q * 4 + 0] = -__expf(v.x);
        a[q * 4 + 1] = -__expf(v.y);
        a[q * 4 + 2] = -__expf(v.z);
        a[q * 4 + 3] = -__expf(v.w);
    }
    float h[kDS], Ep[kDS];
#pragma unroll
    for (int s = 0; s < kDS; s++) { h[s] = 0.f; Ep[s] = 1.f; }

    size_t r0 = (size_t)b * kL + c * kG;
    const float* pdt = dt + r0 * kDI + i;
    const float* pxc = xc + r0 * kDI + i;
    const float* pB  = dbc + r0 * kDBC + kDTR;
    for (int g = 0; g < kG; g++) {
        float dt_t = *pdt, x_t = *pxc;
        float Bv[kDS];
#pragma unroll
        for (int q = 0; q < 4; q++) {
            float4 v = *(const float4*)(pB + q * 4);
            Bv[q * 4 + 0] = v.x; Bv[q * 4 + 1] = v.y;
            Bv[q * 4 + 2] = v.z; Bv[q * 4 + 3] = v.w;
        }
#pragma unroll
        for (int s = 0; s < kDS; s++) {
            float e = __expf(dt_t * a[s]);
            h[s] = fmaf(h[s], e, dt_t * x_t * Bv[s]);
            Ep[s] *= e;
        }
        pdt += kDI; pxc += kDI; pB += kDBC;
    }
    size_t t0 = (size_t)n * kDS;
#pragma unroll
    for (int q = 0; q < 4; q++) {
        *(float4*)(E + t0 + q * 4) = make_float4(Ep[q * 4], Ep[q * 4 + 1],
                                                 Ep[q * 4 + 2], Ep[q * 4 + 3]);
        *(float4*)(U + t0 + q * 4) = make_float4(h[q * 4], h[q * 4 + 1],
                                                 h[q * 4 + 2], h[q * 4 + 3]);
    }
}

__global__ __launch_bounds__(256)
void scan_p2(const float* __restrict__ E,
             const float* __restrict__ U,
             float* __restrict__ H) {
    int t = blockIdx.x * 256 + threadIdx.x;
    int sb = t >> 4;
    int s = t & 15;
    int i = sb % kDI;
    int b = sb / kDI;
    float h = 0.f;
#pragma unroll
    for (int c = 0; c < kNCH; c++) {
        size_t idx = ((((size_t)b * kNCH + c) * kDI + i) << 4) + s;
        H[idx] = h;
        h = fmaf(E[idx], h, U[idx]);
    }
}

__global__ __launch_bounds__(256)
void scan_p3(const float* __restrict__ dt,
             const float* __restrict__ xc,
             const float* __restrict__ dbc,
             const float* __restrict__ xz,
             const float* __restrict__ A_log,
             const float* __restrict__ D_skip,
             const float* __restrict__ H,
             __nv_bfloat16* __restrict__ yh) {
    int n = blockIdx.x * 256 + threadIdx.x;
    if (n >= kScanT) return;
    int i = n % kDI;
    int bc = n / kDI;
    int c = bc & (kNCH - 1);
    int b = bc >> 5;

    float a[kDS];
#pragma unroll
    for (int q = 0; q < 4; q++) {
        float4 v = *(const float4*)(A_log + (size_t)i * kDS + q * 4);
        a[q * 4 + 0] = -__expf(v.x);
        a[q * 4 + 1] = -__expf(v.y);
        a[q * 4 + 2] = -__expf(v.z);
        a[q * 4 + 3] = -__expf(v.w);
    }
    const float dsk = D_skip[i];
    float h[kDS];
    size_t t0 = (size_t)n * kDS;
#pragma unroll
    for (int q = 0; q < 4; q++) {
        float4 v = *(const float4*)(H + t0 + q * 4);
        h[q * 4 + 0] = v.x; h[q * 4 + 1] = v.y;
        h[q * 4 + 2] = v.z; h[q * 4 + 3] = v.w;
    }

    size_t r0 = (size_t)b * kL + c * kG;
    const float* pdt = dt + r0 * kDI + i;
    const float* pxc = xc + r0 * kDI + i;
    const float* pB  = dbc + r0 * kDBC + kDTR;
    const float* pC  = dbc + r0 * kDBC + kDTR + kDS;
    const float* pz  = xz + r0 * (2 * kDI) + kDI + i;
    __nv_bfloat16* pyh = yh + r0 * kDI + i;
    for (int g = 0; g < kG; g++) {
        float dt_t = *pdt, x_t = *pxc;
        float Bv[kDS], Cv[kDS];
#pragma unroll
        for (int q = 0; q < 4; q++) {
            float4 v = *(const float4*)(pB + q * 4);
            Bv[q * 4 + 0] = v.x; Bv[q * 4 + 1] = v.y;
            Bv[q * 4 + 2] = v.z; Bv[q * 4 + 3] = v.w;
            float4 w = *(const float4*)(pC + q * 4);
            Cv[q * 4 + 0] = w.x; Cv[q * 4 + 1] = w.y;
            Cv[q * 4 + 2] = w.z; Cv[q * 4 + 3] = w.w;
        }
        float tmp[kDS];
#pragma unroll
        for (int s = 0; s < kDS; s++) {
            float e = __expf(dt_t * a[s]);
            h[s] = fmaf(h[s], e, dt_t * x_t * Bv[s]);
            tmp[s] = h[s] * Cv[s];
        }
        // pairwise tree sum — same summation tree as the shfl butterfly (lane 0)
#pragma unroll
        for (int st = 8; st > 0; st >>= 1)
#pragma unroll
            for (int s = 0; s < st; s++) tmp[s] += tmp[s + st];
        float z = *pz;
        float yy = fmaf(x_t, dsk, tmp[0]);
        yy *= z / (1.f + __expf(-z));
        *pyh = __float2bfloat16_rn(yy);

        pdt += kDI; pxc += kDI; pB += kDBC; pC += kDBC;
        pz += 2 * kDI; pyh += kDI;
    }
}

// ---------------- final head ----------------
__global__ void head_kernel(const float* __restrict__ xn,
                            const float* __restrict__ cls_w,
                            const float* __restrict__ cls_b,
                            float* __restrict__ out) {
    int b = blockIdx.x;
    __shared__ float mean[kD];
    for (int d = threadIdx.x; d < kD; d += blockDim.x) {
        float s = 0.f;
        const float* p = xn + ((size_t)b * kL) * kD + d;
        for (int l = 0; l < kL; l++) s += p[(size_t)l * kD];
        mean[d] = s / (float)kL;
    }
    __syncthreads();
    if (threadIdx.x < kNC) {
        int c = threadIdx.x;
        float s = cls_b[c];
        for (int d = 0; d < kD; d++) s = fmaf(mean[d], cls_w[c * kD + d], s);
        out[b * kNC + c] = s;
    }
}

// ---------------- launch ----------------
extern "C" void kernel_launch(void* const* d_in, const int* in_sizes, int n_in,
                              void* d_out, int out_size) {
    const int*   input_ids = (const int*)  d_in[0];
    const float* embed     = (const float*)d_in[1];
    const float* norm_w    = (const float*)d_in[2];
    const float* in_proj_w = (const float*)d_in[3];
    const float* conv_w    = (const float*)d_in[4];
    const float* conv_b    = (const float*)d_in[5];
    const float* x_proj_w  = (const float*)d_in[6];
    const float* dt_proj_w = (const float*)d_in[7];
    const float* dt_proj_b = (const float*)d_in[8];
    const float* A_log     = (const float*)d_in[9];
    const float* D_skip    = (const float*)d_in[10];
    const float* out_proj_w= (const float*)d_in[11];
    const float* norm_f_w  = (const float*)d_in[12];
    const float* cls_w     = (const float*)d_in[13];
    const float* cls_b     = (const float*)d_in[14];
    float* out = (float*)d_out;

    float *px, *pxn, *pxz, *pxc, *pdbc, *pdbp, *pdt, *pE, *pU, *pH;
    __nv_bfloat16 *pwinh, *pwinl, *pwouth, *pwoutl, *pxnh, *pyh;
    cudaGetSymbolAddress((void**)&px,    g_x);
    cudaGetSymbolAddress((void**)&pxn,   g_xn);
    cudaGetSymbolAddress((void**)&pxz,   g_xz);
    cudaGetSymbolAddress((void**)&pxc,   g_xc);
    cudaGetSymbolAddress((void**)&pdbc,  g_dbc);
    cudaGetSymbolAddress((void**)&pdbp,  g_dbp);
    cudaGetSymbolAddress((void**)&pdt,   g_dt);
    cudaGetSymbolAddress((void**)&pE,    g_E);
    cudaGetSymbolAddress((void**)&pU,    g_U);
    cudaGetSymbolAddress((void**)&pH,    g_H);
    cudaGetSymbolAddress((void**)&pwinh, g_winh);
    cudaGetSymbolAddress((void**)&pwinl, g_winl);
    cudaGetSymbolAddress((void**)&pwouth,g_wouth);
    cudaGetSymbolAddress((void**)&pwoutl,g_woutl);
    cudaGetSymbolAddress((void**)&pxnh,  g_xnh);
    cudaGetSymbolAddress((void**)&pyh,   g_yh);

    cudaFuncSetAttribute(hgemm_ps_kernel<0, 128>,
                         cudaFuncAttributeMaxDynamicSharedMemorySize, kSmem128);
    cudaFuncSetAttribute(hgemm_ps_kernel<1, 64>,
                         cudaFuncAttributeMaxDynamicSharedMemorySize, kSmem64);

    const int sBlocks = (kScanT + 255) / 256;     // 384
    const int p2Blocks = (kB * kDI * kDS) / 256;  // 192

    // launch 0: embed, 1: split_in, 2: rmsnorm(L0), 3: in_proj <- ncu capture
    {
        int total = kRows * kD / 4;
        embed_kernel<<<(total + 255) / 256, 256>>>(input_ids, embed, px);
    }
    {
        int n4 = kInWN / 4;
        split_f32_kernel<<<(n4 + 255) / 256, 256>>>(in_proj_w, pwinh, pwinl, n4);
    }

    for (int l = 0; l < kNL; l++) {
        const float* w_norm = norm_w    + (size_t)l * kD;
        const float* w_cw   = conv_w    + (size_t)l * kDI * kDC;
        const float* w_cb   = conv_b    + (size_t)l * kDI;
        const float* w_xp   = x_proj_w  + (size_t)l * kDBC * kDI;
        const float* w_dtw  = dt_proj_w + (size_t)l * kDI * kDTR;
        const float* w_dtb  = dt_proj_b + (size_t)l * kDI;
        const float* w_Al   = A_log     + (size_t)l * kDI * kDS;
        const float* w_Dsk  = D_skip    + (size_t)l * kDI;
        const __nv_bfloat16* w_inh  = pwinh  + (size_t)l * 2 * kDI * kD;
        const __nv_bfloat16* w_inl  = pwinl  + (size_t)l * 2 * kDI * kD;
        const __nv_bfloat16* w_outh = pwouth + (size_t)l * kD * kDI;
        const __nv_bfloat16* w_outl = pwoutl + (size_t)l * kD * kDI;

        // rmsnorm -> bf16 hi plane
        rmsnorm_kernel<true><<<kRows, 256>>>(px, w_norm, nullptr, pxnh);

        // in_proj: pre-split 2-term, 128x128 tiles, 3-stage pipeline
        {
            dim3 grid(2 * kDI / 128, kRows / 128);   // (24,16)
            hgemm_ps_kernel<0, 128><<<grid, 256, kSmem128>>>(
                pxnh, w_inh, w_inl, pxz, 2 * kDI, kD);
        }

        // conv + silu (float4)
        {
            int total = kRows * kDI / 4;
            conv_silu_kernel<<<(total + 255) / 256, 256>>>(pxz, w_cw, w_cb, pxc);
        }

        // x_proj split-K
        {
            dim3 grid(2, kRows / 64, kXPChunks);
            gemm_xproj_splitk<<<grid, 256>>>(pxc, w_xp, pdbp);
            int total = kRows * kDBC;
            reduce_dbc_kernel<<<(total + 255) / 256, 256>>>(pdbp, pdbc);
        }

        // dt (fp32, K=48)
        {
            dim3 grid(kDI / 128, kRows / 128);
            sgemm_tn_kernel<2, 128><<<grid, 256>>>(pdbc, kDBC, w_dtw, pdt, kDI,
                                                   w_dtb, kRows, kDI, kDTR);
        }

        // chunked selective scan (register-state p1/p3)
        scan_p1<<<sBlocks, 256>>>(pdt, pxc, pdbc, w_Al, pE, pU);
        scan_p2<<<p2Blocks, 256>>>(pE, pU, pH);
        scan_p3<<<sBlocks, 256>>>(pdt, pxc, pdbc, pxz, w_Al, w_Dsk, pH, pyh);

        // split out_proj weights once, before first use
        if (l == 0) {
            int n4 = kOutWN / 4;
            split_f32_kernel<<<(n4 + 255) / 256, 256>>>(out_proj_w, pwouth, pwoutl, n4);
        }

        // out_proj + residual: pre-split 2-term, 64x128 tiles, 3-stage pipeline
        {
            dim3 grid(kD / 128, kRows / 64);         // (6,32)
            hgemm_ps_kernel<1, 64><<<grid, 256, kSmem64>>>(
                pyh, w_outh, w_outl, px, kD, kDI);
        }
    }

    rmsnorm_kernel<false><<<kRows, 256>>>(px, norm_f_w, pxn, nullptr);
    head_kernel<<<kB, 256>>>(pxn, cls_w, cls_b, out);
}

// round 15
// speedup vs baseline: 1.3578x; 1.0185x over previous
#include <cuda_runtime.h>
#include <cuda_bf16.h>
#include <math.h>
#include <stdint.h>

// ---------------- problem constants ----------------
constexpr int kV   = 50280;
constexpr int kD   = 768;
constexpr int kNL  = 8;
constexpr int kDI  = 1536;
constexpr int kDS  = 16;
constexpr int kDC  = 4;
constexpr int kDTR = 48;
constexpr int kNC  = 4;
constexpr int kB   = 2;
constexpr int kL   = 1024;
constexpr int kDBC = kDTR + 2 * kDS;  // 80
constexpr float kEPS = 1e-5f;

constexpr int kRows = kB * kL;        // 2048
constexpr int kXPChunks = 8;
constexpr int kXPKC = kDI / kXPChunks; // 192

// chunked scan
constexpr int kG   = 32;
constexpr int kNCH = kL / kG;         // 32
constexpr int kScanN = kB * kNCH * kDI * kDS;   // 1.57M
constexpr int kScanT = kB * kNCH * kDI;         // 98304 threads

constexpr int kInWN  = kNL * 2 * kDI * kD;   // 18.9M
constexpr int kOutWN = kNL * kD * kDI;       // 9.4M

// ---------------- device scratch ----------------
__device__ float g_x  [kRows * kD];
__device__ float g_xn [kRows * kD];          // fp32 (final norm only)
__device__ float g_xz [kRows * 2 * kDI];
__device__ float g_xc [kRows * kDI];
__device__ float g_dbc[kRows * kDBC];
__device__ float g_dbp[kXPChunks * kRows * kDBC];
__device__ float g_dt [kRows * kDI];
__device__ float g_E  [kScanN];
__device__ float g_U  [kScanN];
__device__ float g_H  [kScanN];

__device__ __align__(16) __nv_bfloat16 g_winh[kInWN];
__device__ __align__(16) __nv_bfloat16 g_winl[kInWN];
__device__ __align__(16) __nv_bfloat16 g_wouth[kOutWN];
__device__ __align__(16) __nv_bfloat16 g_woutl[kOutWN];
__device__ __align__(16) __nv_bfloat16 g_xnh[kRows * kD];
__device__ __align__(16) __nv_bfloat16 g_yh [kRows * kDI];

// ---------------- helpers ----------------
__device__ __forceinline__ float warp_sum(float v) {
#pragma unroll
    for (int o = 16; o > 0; o >>= 1) v += __shfl_xor_sync(0xffffffffu, v, o);
    return v;
}
__device__ __forceinline__ uint32_t smem_u32(const void* p) {
    return (uint32_t)__cvta_generic_to_shared(p);
}
__device__ __forceinline__ void ldmat_x4(uint32_t& r0, uint32_t& r1,
                                         uint32_t& r2, uint32_t& r3,
                                         uint32_t addr) {
    asm volatile("ldmatrix.sync.aligned.m8n8.x4.shared.b16 {%0,%1,%2,%3}, [%4];"
                 : "=r"(r0), "=r"(r1), "=r"(r2), "=r"(r3) : "r"(addr));
}
__device__ __forceinline__ void mma16816(float* c, const uint32_t* a,
                                         uint32_t b0, uint32_t b1) {
    asm volatile(
        "mma.sync.aligned.m16n8k16.row.col.f32.bf16.bf16.f32 "
        "{%0,%1,%2,%3}, {%4,%5,%6,%7}, {%8,%9}, {%0,%1,%2,%3};"
        : "+f"(c[0]), "+f"(c[1]), "+f"(c[2]), "+f"(c[3])
        : "r"(a[0]), "r"(a[1]), "r"(a[2]), "r"(a[3]), "r"(b0), "r"(b1));
}
__device__ __forceinline__ void cp16(uint32_t dst, const void* src) {
    asm volatile("cp.async.cg.shared.global [%0], [%1], 16;\n" :: "r"(dst), "l"(src));
}
__device__ __forceinline__ void cp_commit() {
    asm volatile("cp.async.commit_group;\n");
}
template <int N>
__device__ __forceinline__ void cp_wait() {
    asm volatile("cp.async.wait_group %0;\n" :: "n"(N));
}

// ---------------- weight hi/lo split ----------------
__global__ void split_f32_kernel(const float* __restrict__ src,
                                 __nv_bfloat16* __restrict__ h,
                                 __nv_bfloat16* __restrict__ l, int n4) {
    int i = blockIdx.x * blockDim.x + threadIdx.x;
    if (i >= n4) return;
    float4 v = ((const float4*)src)[i];
    __nv_bfloat162 h01 = __floats2bfloat162_rn(v.x, v.y);
    __nv_bfloat162 h23 = __floats2bfloat162_rn(v.z, v.w);
    __nv_bfloat162 l01 = __floats2bfloat162_rn(v.x - __bfloat162float(h01.x),
                                               v.y - __bfloat162float(h01.y));
    __nv_bfloat162 l23 = __floats2bfloat162_rn(v.z - __bfloat162float(h23.x),
                                               v.w - __bfloat162float(h23.y));
    ((__nv_bfloat162*)h)[i * 2]     = h01;
    ((__nv_bfloat162*)h)[i * 2 + 1] = h23;
    ((__nv_bfloat162*)l)[i * 2]     = l01;
    ((__nv_bfloat162*)l)[i * 2 + 1] = l23;
}

// ---------------- embed gather ----------------
__global__ void embed_kernel(const int* __restrict__ ids,
                             const float* __restrict__ embed,
                             float* __restrict__ x) {
    int idx = blockIdx.x * blockDim.x + threadIdx.x;
    int total = kRows * kD / 4;
    if (idx >= total) return;
    int row = idx / (kD / 4);
    int d4 = idx - row * (kD / 4);
    const float4* src = (const float4*)(embed + (size_t)ids[row] * kD);
    ((float4*)x)[idx] = src[d4];
}

// ---------------- rmsnorm (float4): SPLIT -> bf16 hi plane; else fp32 -------
template <bool SPLIT>
__global__ void rmsnorm_kernel(const float* __restrict__ x,
                               const float* __restrict__ w,
                               float* __restrict__ outf,
                               __nv_bfloat16* __restrict__ outh) {
    int row = blockIdx.x;
    const float4* xr = (const float4*)(x + (size_t)row * kD);
    float s = 0.f;
    for (int d4 = threadIdx.x; d4 < kD / 4; d4 += blockDim.x) {
        float4 v = xr[d4];
        s = fmaf(v.x, v.x, s);
        s = fmaf(v.y, v.y, s);
        s = fmaf(v.z, v.z, s);
        s = fmaf(v.w, v.w, s);
    }
    s = warp_sum(s);
    __shared__ float sh[8];
    __shared__ float inv_s;
    int wid = threadIdx.x >> 5, lane = threadIdx.x & 31;
    if (lane == 0) sh[wid] = s;
    __syncthreads();
    if (wid == 0) {
        float t = (lane < (blockDim.x >> 5)) ? sh[lane] : 0.f;
        t = warp_sum(t);
        if (lane == 0) inv_s = rsqrtf(t / (float)kD + kEPS);
    }
    __syncthreads();
    float inv = inv_s;
    const float4* wr = (const float4*)w;
    for (int d4 = threadIdx.x; d4 < kD / 4; d4 += blockDim.x) {
        float4 v = xr[d4];
        float4 ww = wr[d4];
        v.x = v.x * inv * ww.x;
        v.y = v.y * inv * ww.y;
        v.z = v.z * inv * ww.z;
        v.w = v.w * inv * ww.w;
        if (SPLIT) {
            __nv_bfloat162* o = (__nv_bfloat162*)(outh + (size_t)row * kD + d4 * 4);
            o[0] = __floats2bfloat162_rn(v.x, v.y);
            o[1] = __floats2bfloat162_rn(v.z, v.w);
        } else {
            ((float4*)(outf + (size_t)row * kD))[d4] = v;
        }
    }
}

// =====================================================================
// Pre-split bf16 tensor-core GEMM, 3-stage cp.async, single sync/kt.
//   C[M,N] = Ah[M,K] @ (Bh + Bl)[N,K]^T
//   BM in {64,128}, BN=128, BK=32, 256 threads (8 warps: 2 in M, 4 in N)
// EPI 0: store    EPI 1: C += result
// =====================================================================
template <int EPI, int BM>
__global__ __launch_bounds__(256, 2)
void hgemm_ps_kernel(const __nv_bfloat16* __restrict__ Ah,
                     const __nv_bfloat16* __restrict__ Bh,
                     const __nv_bfloat16* __restrict__ Bl,
                     float* __restrict__ C, int ldc, int K) {
    constexpr int BN = 128, BK = 32;
    constexpr int STR = 40;
    constexpr int WM = BM / 2;
    constexpr int MF = WM / 16;
    constexpr int ASZ = BM * STR;
    constexpr int BSZ = BN * STR;
    constexpr int ACH = BM / 64;
    constexpr int ST = 3;

    extern __shared__ __nv_bfloat16 sm[];
    __nv_bfloat16* As_h = sm;
    __nv_bfloat16* Bs_h = As_h + ST * ASZ;
    __nv_bfloat16* Bs_l = Bs_h + ST * BSZ;

    const int tid = threadIdx.x;
    const int wid = tid >> 5, lane = tid & 31;
    const int bm0 = blockIdx.y * BM;
    const int bn0 = blockIdx.x * BN;
    const int wm = wid & 1;
    const int wn = wid >> 1;

    float acc[MF][4][4];
#pragma unroll
    for (int i = 0; i < MF; i++)
#pragma unroll
        for (int j = 0; j < 4; j++)
#pragma unroll
            for (int v = 0; v < 4; v++) acc[i][j][v] = 0.f;

    auto issue_loads = [&](int buf, int k0) {
#pragma unroll
        for (int u = 0; u < ACH; u++) {
            int id = tid + u * 256;
            int r = id >> 2, c8 = (id & 3) * 8;
            size_t g = (size_t)(bm0 + r) * K + k0 + c8;
            cp16(smem_u32(As_h + buf * ASZ + r * STR + c8), Ah + g);
        }
#pragma unroll
        for (int u = 0; u < 2; u++) {
            int id = tid + u * 256;
            int r = id >> 2, c8 = (id & 3) * 8;
            size_t g = (size_t)(bn0 + r) * K + k0 + c8;
            uint32_t soff = (uint32_t)(buf * BSZ + r * STR + c8);
            cp16(smem_u32(Bs_h + soff), Bh + g);
            cp16(smem_u32(Bs_l + soff), Bl + g);
        }
    };

    const int a_row = wm * WM + (lane & 15);
    const int a_col8 = (lane >> 4) << 3;
    const int b_grp = lane >> 3;
    const int b_row = wn * 32 + ((b_grp >> 1) << 3) + (lane & 7);
    const int b_col8 = (b_grp & 1) << 3;

    const int KT = K / BK;
    issue_loads(0, 0);
    cp_commit();
    if (KT > 1) { issue_loads(1, BK); cp_commit(); }

    for (int kt = 0; kt < KT; kt++) {
        if (kt + 1 < KT) cp_wait<1>(); else cp_wait<0>();
        __syncthreads();
        if (kt + 2 < KT) {
            issue_loads((kt + 2) % ST, (kt + 2) * BK);
            cp_commit();
        }
        const int buf = kt % ST;

#pragma unroll
        for (int kk = 0; kk < 2; kk++) {
            uint32_t ah[MF][4];
            uint32_t bh[4][2], bl[4][2];
#pragma unroll
            for (int i = 0; i < MF; i++) {
                uint32_t off = (uint32_t)(buf * ASZ + (a_row + i * 16) * STR
                                          + kk * 16 + a_col8);
                ldmat_x4(ah[i][0], ah[i][1], ah[i][2], ah[i][3],
                         smem_u32(As_h + off));
            }
#pragma unroll
            for (int jj = 0; jj < 2; jj++) {
                uint32_t off = (uint32_t)(buf * BSZ + (b_row + jj * 16) * STR
                                          + kk * 16 + b_col8);
                ldmat_x4(bh[jj * 2][0], bh[jj * 2][1],
                         bh[jj * 2 + 1][0], bh[jj * 2 + 1][1],
                         smem_u32(Bs_h + off));
                ldmat_x4(bl[jj * 2][0], bl[jj * 2][1],
                         bl[jj * 2 + 1][0], bl[jj * 2 + 1][1],
                         smem_u32(Bs_l + off));
            }
#pragma unroll
            for (int i = 0; i < MF; i++)
#pragma unroll
                for (int j = 0; j < 4; j++) {
                    mma16816(acc[i][j], ah[i], bh[j][0], bh[j][1]);
                    mma16816(acc[i][j], ah[i], bl[j][0], bl[j][1]);
                }
        }
    }

    const int c_row = bm0 + wm * WM + (lane >> 2);
    const int c_col = bn0 + wn * 32 + (lane & 3) * 2;
#pragma unroll
    for (int i = 0; i < MF; i++) {
#pragma unroll
        for (int j = 0; j < 4; j++) {
#pragma unroll
            for (int half = 0; half < 2; half++) {
                int gm = c_row + i * 16 + half * 8;
                int gn = c_col + j * 8;
                float* cp = C + (size_t)gm * ldc + gn;
                float v0 = acc[i][j][half * 2 + 0];
                float v1 = acc[i][j][half * 2 + 1];
                if (EPI == 1) {
                    float2 old = *(const float2*)cp;
                    v0 += old.x; v1 += old.y;
                }
                *(float2*)cp = make_float2(v0, v1);
            }
        }
    }
}

constexpr int kSmem128 = 3 * (128 * 40 + 2 * 128 * 40) * 2;  // 92160
constexpr int kSmem64  = 3 * (64 * 40 + 2 * 128 * 40) * 2;   // 76800

// =====================================================================
// fp32 GEMM (dt_proj, K=48)
// =====================================================================
template <int EPI, int BMt>
__global__ __launch_bounds__(256)
void sgemm_tn_kernel(const float* __restrict__ A, int lda,
                     const float* __restrict__ Bw,
                     float* __restrict__ C, int ldc,
                     const float* __restrict__ bias,
                     int M, int N, int K) {
    constexpr int BN = 128, BK = 8;
    constexpr int MR = BMt / 16;
    constexpr int AE = BMt * BK / 256;
    __shared__ float As[2][BK][BMt + 4];
    __shared__ float Bs[2][BK][BN + 4];

    const int tid = threadIdx.x;
    const int bm0 = blockIdx.y * BMt;
    const int bn0 = blockIdx.x * BN;
    const int tx = tid & 15;
    const int ty = tid >> 4;

    const int blr = tid >> 1;
    const int bk4 = (tid & 1) * 4;
    const int gnb = bn0 + blr;
    const bool bvalid = (gnb < N);
    const float* Bbase = Bw + (size_t)gnb * K + bk4;

    float aR[AE];
    float4 bR;

#pragma unroll
    for (int u = 0; u < AE; u++) {
        int e = tid + u * 256;
        int r = e >> 3, k = e & 7;
        aR[u] = A[(size_t)(bm0 + r) * lda + k];
    }
    bR = bvalid ? *(const float4*)Bbase : make_float4(0.f, 0.f, 0.f, 0.f);
#pragma unroll
    for (int u = 0; u < AE; u++) {
        int e = tid + u * 256;
        As[0][e & 7][e >> 3] = aR[u];
    }
    Bs[0][bk4 + 0][blr] = bR.x;
    Bs[0][bk4 + 1][blr] = bR.y;
    Bs[0][bk4 + 2][blr] = bR.z;
    Bs[0][bk4 + 3][blr] = bR.w;
    __syncthreads();

    float acc[MR][8];
#pragma unroll
    for (int i = 0; i < MR; i++)
#pragma unroll
        for (int j = 0; j < 8; j++) acc[i][j] = 0.f;

    const int KT = K / BK;
    int buf = 0;
    for (int kt = 0; kt < KT; kt++) {
        if (kt + 1 < KT) {
            const int k0 = (kt + 1) * BK;
#pragma unroll
            for (int u = 0; u < AE; u++) {
                int e = tid + u * 256;
                int r = e >> 3, k = e & 7;
                aR[u] = A[(size_t)(bm0 + r) * lda + k0 + k];
            }
            bR = bvalid ? *(const float4*)(Bbase + k0) : make_float4(0.f, 0.f, 0.f, 0.f);
        }
#pragma unroll
        for (int k = 0; k < BK; k++) {
            float a[MR], b[8];
            {
                float4 a0 = *(const float4*)&As[buf][k][ty * 4];
                a[0] = a0.x; a[1] = a0.y; a[2] = a0.z; a[3] = a0.w;
                if (MR == 8) {
                    float4 a1 = *(const float4*)&As[buf][k][ty * 4 + 64];
                    a[4] = a1.x; a[5] = a1.y; a[6] = a1.z; a[7] = a1.w;
                }
                float4 b0 = *(const float4*)&Bs[buf][k][tx * 4];
                float4 b1 = *(const float4*)&Bs[buf][k][tx * 4 + 64];
                b[0] = b0.x; b[1] = b0.y; b[2] = b0.z; b[3] = b0.w;
                b[4] = b1.x; b[5] = b1.y; b[6] = b1.z; b[7] = b1.w;
            }
#pragma unroll
            for (int i = 0; i < MR; i++)
#pragma unroll
                for (int j = 0; j < 8; j++)
                    acc[i][j] = fmaf(a[i], b[j], acc[i][j]);
        }
        if (kt + 1 < KT) {
            int nb = buf ^ 1;
#pragma unroll
            for (int u = 0; u < AE; u++) {
                int e = tid + u * 256;
                As[nb][e & 7][e >> 3] = aR[u];
            }
            Bs[nb][bk4 + 0][blr] = bR.x;
            Bs[nb][bk4 + 1][blr] = bR.y;
            Bs[nb][bk4 + 2][blr] = bR.z;
            Bs[nb][bk4 + 3][blr] = bR.w;
            __syncthreads();
            buf = nb;
        }
    }

#pragma unroll
    for (int i = 0; i < MR; i++) {
        int gm = bm0 + ty * 4 + (i & 3) + (i >> 2) * 64;
#pragma unroll
        for (int jj = 0; jj < 2; jj++) {
            int gn = bn0 + tx * 4 + jj * 64;
            if (gn >= N) continue;
            float v0 = acc[i][jj * 4 + 0];
            float v1 = acc[i][jj * 4 + 1];
            float v2 = acc[i][jj * 4 + 2];
            float v3 = acc[i][jj * 4 + 3];
            float* cp = C + (size_t)gm * ldc + gn;
            if (EPI == 1) {
                float4 old = *(const float4*)cp;
                v0 += old.x; v1 += old.y; v2 += old.z; v3 += old.w;
            }
            if (EPI == 2) {
                float bb[4] = {bias[gn], bias[gn + 1], bias[gn + 2], bias[gn + 3]};
                v0 += bb[0]; v1 += bb[1]; v2 += bb[2]; v3 += bb[3];
                v0 = fmaxf(v0, 0.f) + log1pf(expf(-fabsf(v0)));
                v1 = fmaxf(v1, 0.f) + log1pf(expf(-fabsf(v1)));
                v2 = fmaxf(v2, 0.f) + log1pf(expf(-fabsf(v2)));
                v3 = fmaxf(v3, 0.f) + log1pf(expf(-fabsf(v3)));
            }
            *(float4*)cp = make_float4(v0, v1, v2, v3);
        }
    }
}

// =====================================================================
// x_proj split-K GEMM + reduce
// =====================================================================
__global__ void gemm_xproj_splitk(const float* __restrict__ A,
                                  const float* __restrict__ Bw,
                                  float* __restrict__ part) {
    constexpr int BM = 64, BN = 64, BK = 16;
    __shared__ float As[BK][BM + 4];
    __shared__ float Bs[BK][BN + 4];
    const int tid = threadIdx.x;
    const int bm0 = blockIdx.y * BM;
    const int bn0 = blockIdx.x * BN;
    const int zoff = blockIdx.z * kXPKC;
    const int tx = tid & 15;
    const int ty = tid >> 4;
    float acc[4][4] = {};

    for (int k0 = 0; k0 < kXPKC; k0 += BK) {
#pragma unroll
        for (int t = tid; t < BM * BK; t += 256) {
            int m = t >> 4, k = t & 15;
            As[k][m] = A[(size_t)(bm0 + m) * kDI + zoff + k0 + k];
        }
#pragma unroll
        for (int t = tid; t < BN * BK; t += 256) {
            int n = t >> 4, k = t & 15;
            int gn = bn0 + n;
            Bs[k][n] = (gn < kDBC) ? Bw[(size_t)gn * kDI + zoff + k0 + k] : 0.f;
        }
        __syncthreads();
#pragma unroll
        for (int k = 0; k < BK; k++) {
            float a[4], b[4];
#pragma unroll
            for (int i = 0; i < 4; i++) a[i] = As[k][ty * 4 + i];
#pragma unroll
            for (int j = 0; j < 4; j++) b[j] = Bs[k][tx * 4 + j];
#pragma unroll
            for (int i = 0; i < 4; i++)
#pragma unroll
                for (int j = 0; j < 4; j++)
                    acc[i][j] = fmaf(a[i], b[j], acc[i][j]);
        }
        __syncthreads();
    }

    float* base = part + (size_t)blockIdx.z * kRows * kDBC;
#pragma unroll
    for (int i = 0; i < 4; i++) {
        int gm = bm0 + ty * 4 + i;
#pragma unroll
        for (int j = 0; j < 4; j++) {
            int gn = bn0 + tx * 4 + j;
            if (gn < kDBC) base[(size_t)gm * kDBC + gn] = acc[i][j];
        }
    }
}

__global__ void reduce_dbc_kernel(const float* __restrict__ part,
                                  float* __restrict__ dbc) {
    int idx = blockIdx.x * blockDim.x + threadIdx.x;
    if (idx >= kRows * kDBC) return;
    float s = 0.f;
#pragma unroll
    for (int z = 0; z < kXPChunks; z++)
        s += part[(size_t)z * kRows * kDBC + idx];
    dbc[idx] = s;
}

// ---------------- causal depthwise conv (DC=4) + SiLU, float4 ----------------
__global__ void conv_silu_kernel(const float* __restrict__ xz,
                                 const float* __restrict__ cw,
                                 const float* __restrict__ cb,
                                 float* __restrict__ xc) {
    int idx = blockIdx.x * blockDim.x + threadIdx.x;
    int total = kRows * kDI / 4;
    if (idx >= total) return;
    int i4 = idx % (kDI / 4);
    int r = idx / (kDI / 4);
    int l = r % kL;
    int b = r / kL;
    int i = i4 * 4;

    float4 acc = *(const float4*)(cb + i);
#pragma unroll
    for (int k = 0; k < kDC; k++) {
        int ls = l + k - (kDC - 1);
        if (ls >= 0) {
            const float4 xv = *(const float4*)(xz + ((size_t)(b * kL + ls)) * (2 * kDI) + i);
            acc.x = fmaf(xv.x, cw[(i + 0) * kDC + k], acc.x);
            acc.y = fmaf(xv.y, cw[(i + 1) * kDC + k], acc.y);
            acc.z = fmaf(xv.z, cw[(i + 2) * kDC + k], acc.z);
            acc.w = fmaf(xv.w, cw[(i + 3) * kDC + k], acc.w);
        }
    }
    acc.x = acc.x / (1.f + __expf(-acc.x));
    acc.y = acc.y / (1.f + __expf(-acc.y));
    acc.z = acc.z / (1.f + __expf(-acc.z));
    acc.w = acc.w / (1.f + __expf(-acc.w));
    *(float4*)(xc + (size_t)r * kDI + i) = acc;
}

// =====================================================================
// chunked selective scan — register-state version (128-thread blocks)
// =====================================================================
__global__ __launch_bounds__(128)
void scan_p1(const float* __restrict__ dt,
             const float* __restrict__ xc,
             const float* __restrict__ dbc,
             const float* __restrict__ A_log,
             float* __restrict__ E, float* __restrict__ U) {
    int n = blockIdx.x * blockDim.x + threadIdx.x;
    if (n >= kScanT) return;
    int i = n % kDI;
    int bc = n / kDI;
    int c = bc & (kNCH - 1);
    int b = bc >> 5;

    float a[kDS];
#pragma unroll
    for (int q = 0; q < 4; q++) {
        float4 v = *(const float4*)(A_log + (size_t)i * kDS + q * 4);
        a[q * 4 + 0] = -__expf(v.x);
        a[q * 4 + 1] = -__expf(v.y);
        a[q * 4 + 2] = -__expf(v.z);
        a[q * 4 + 3] = -__expf(v.w);
    }
    float h[kDS], Ep[kDS];
#pragma unroll
    for (int s = 0; s < kDS; s++) { h[s] = 0.f; Ep[s] = 1.f; }

    size_t r0 = (size_t)b * kL + c * kG;
    const float* pdt = dt + r0 * kDI + i;
    const float* pxc = xc + r0 * kDI + i;
    const float* pB  = dbc + r0 * kDBC + kDTR;
    for (int g = 0; g < kG; g++) {
        float dt_t = *pdt, x_t = *pxc;
        float Bv[kDS];
#pragma unroll
        for (int q = 0; q < 4; q++) {
            float4 v = *(const float4*)(pB + q * 4);
            Bv[q * 4 + 0] = v.x; Bv[q * 4 + 1] = v.y;
            Bv[q * 4 + 2] = v.z; Bv[q * 4 + 3] = v.w;
        }
#pragma unroll
        for (int s = 0; s < kDS; s++) {
            float e = __expf(dt_t * a[s]);
            h[s] = fmaf(h[s], e, dt_t * x_t * Bv[s]);
            Ep[s] *= e;
        }
        pdt += kDI; pxc += kDI; pB += kDBC;
    }
    size_t t0 = (size_t)n * kDS;
#pragma unroll
    for (int q = 0; q < 4; q++) {
        *(float4*)(E + t0 + q * 4) = make_float4(Ep[q * 4], Ep[q * 4 + 1],
                                                 Ep[q * 4 + 2], Ep[q * 4 + 3]);
        *(float4*)(U + t0 + q * 4) = make_float4(h[q * 4], h[q * 4 + 1],
                                                 h[q * 4 + 2], h[q * 4 + 3]);
    }
}

__global__ __launch_bounds__(128)
void scan_p2(const float* __restrict__ E,
             const float* __restrict__ U,
             float* __restrict__ H) {
    int t = blockIdx.x * blockDim.x + threadIdx.x;
    int sb = t >> 4;
    int s = t & 15;
    int i = sb % kDI;
    int b = sb / kDI;
    float h = 0.f;
#pragma unroll
    for (int c = 0; c < kNCH; c++) {
        size_t idx = ((((size_t)b * kNCH + c) * kDI + i) << 4) + s;
        H[idx] = h;
        h = fmaf(E[idx], h, U[idx]);
    }
}

__global__ __launch_bounds__(128)
void scan_p3(const float* __restrict__ dt,
             const float* __restrict__ xc,
             const float* __restrict__ dbc,
             const float* __restrict__ xz,
             const float* __restrict__ A_log,
             const float* __restrict__ D_skip,
             const float* __restrict__ H,
             __nv_bfloat16* __restrict__ yh) {
    int n = blockIdx.x * blockDim.x + threadIdx.x;
    if (n >= kScanT) return;
    int i = n % kDI;
    int bc = n / kDI;
    int c = bc & (kNCH - 1);
    int b = bc >> 5;

    float a[kDS];
#pragma unroll
    for (int q = 0; q < 4; q++) {
        float4 v = *(const float4*)(A_log + (size_t)i * kDS + q * 4);
        a[q * 4 + 0] = -__expf(v.x);
        a[q * 4 + 1] = -__expf(v.y);
        a[q * 4 + 2] = -__expf(v.z);
        a[q * 4 + 3] = -__expf(v.w);
    }
    const float dsk = D_skip[i];
    float h[kDS];
    size_t t0 = (size_t)n * kDS;
#pragma unroll
    for (int q = 0; q < 4; q++) {
        float4 v = *(const float4*)(H + t0 + q * 4);
        h[q * 4 + 0] = v.x; h[q * 4 + 1] = v.y;
        h[q * 4 + 2] = v.z; h[q * 4 + 3] = v.w;
    }

    size_t r0 = (size_t)b * kL + c * kG;
    const float* pdt = dt + r0 * kDI + i;
    const float* pxc = xc + r0 * kDI + i;
    const float* pB  = dbc + r0 * kDBC + kDTR;
    const float* pC  = dbc + r0 * kDBC + kDTR + kDS;
    const float* pz  = xz + r0 * (2 * kDI) + kDI + i;
    __nv_bfloat16* pyh = yh + r0 * kDI + i;
    for (int g = 0; g < kG; g++) {
        float dt_t = *pdt, x_t = *pxc;
        float Bv[kDS], Cv[kDS];
#pragma unroll
        for (int q = 0; q < 4; q++) {
            float4 v = *(const float4*)(pB + q * 4);
            Bv[q * 4 + 0] = v.x; Bv[q * 4 + 1] = v.y;
            Bv[q * 4 + 2] = v.z; Bv[q * 4 + 3] = v.w;
            float4 w = *(const float4*)(pC + q * 4);
            Cv[q * 4 + 0] = w.x; Cv[q * 4 + 1] = w.y;
            Cv[q * 4 + 2] = w.z; Cv[q * 4 + 3] = w.w;
        }
        float tmp[kDS];
#pragma unroll
        for (int s = 0; s < kDS; s++) {
            float e = __expf(dt_t * a[s]);
            h[s] = fmaf(h[s], e, dt_t * x_t * Bv[s]);
            tmp[s] = h[s] * Cv[s];
        }
#pragma unroll
        for (int st = 8; st > 0; st >>= 1)
#pragma unroll
            for (int s = 0; s < st; s++) tmp[s] += tmp[s + st];
        float z = *pz;
        float yy = fmaf(x_t, dsk, tmp[0]);
        yy *= z / (1.f + __expf(-z));
        *pyh = __float2bfloat16_rn(yy);

        pdt += kDI; pxc += kDI; pB += kDBC; pC += kDBC;
        pz += 2 * kDI; pyh += kDI;
    }
}

// ---------------- final head ----------------
__global__ void head_kernel(const float* __restrict__ xn,
                            const float* __restrict__ cls_w,
                            const float* __restrict__ cls_b,
                            float* __restrict__ out) {
    int b = blockIdx.x;
    __shared__ float mean[kD];
    for (int d = threadIdx.x; d < kD; d += blockDim.x) {
        float s = 0.f;
        const float* p = xn + ((size_t)b * kL) * kD + d;
        for (int l = 0; l < kL; l++) s += p[(size_t)l * kD];
        mean[d] = s / (float)kL;
    }
    __syncthreads();
    if (threadIdx.x < kNC) {
        int c = threadIdx.x;
        float s = cls_b[c];
        for (int d = 0; d < kD; d++) s = fmaf(mean[d], cls_w[c * kD + d], s);
        out[b * kNC + c] = s;
    }
}

// ---------------- launch ----------------
extern "C" void kernel_launch(void* const* d_in, const int* in_sizes, int n_in,
                              void* d_out, int out_size) {
    const int*   input_ids = (const int*)  d_in[0];
    const float* embed     = (const float*)d_in[1];
    const float* norm_w    = (const float*)d_in[2];
    const float* in_proj_w = (const float*)d_in[3];
    const float* conv_w    = (const float*)d_in[4];
    const float* conv_b    = (const float*)d_in[5];
    const float* x_proj_w  = (const float*)d_in[6];
    const float* dt_proj_w = (const float*)d_in[7];
    const float* dt_proj_b = (const float*)d_in[8];
    const float* A_log     = (const float*)d_in[9];
    const float* D_skip    = (const float*)d_in[10];
    const float* out_proj_w= (const float*)d_in[11];
    const float* norm_f_w  = (const float*)d_in[12];
    const float* cls_w     = (const float*)d_in[13];
    const float* cls_b     = (const float*)d_in[14];
    float* out = (float*)d_out;

    float *px, *pxn, *pxz, *pxc, *pdbc, *pdbp, *pdt, *pE, *pU, *pH;
    __nv_bfloat16 *pwinh, *pwinl, *pwouth, *pwoutl, *pxnh, *pyh;
    cudaGetSymbolAddress((void**)&px,    g_x);
    cudaGetSymbolAddress((void**)&pxn,   g_xn);
    cudaGetSymbolAddress((void**)&pxz,   g_xz);
    cudaGetSymbolAddress((void**)&pxc,   g_xc);
    cudaGetSymbolAddress((void**)&pdbc,  g_dbc);
    cudaGetSymbolAddress((void**)&pdbp,  g_dbp);
    cudaGetSymbolAddress((void**)&pdt,   g_dt);
    cudaGetSymbolAddress((void**)&pE,    g_E);
    cudaGetSymbolAddress((void**)&pU,    g_U);
    cudaGetSymbolAddress((void**)&pH,    g_H);
    cudaGetSymbolAddress((void**)&pwinh, g_winh);
    cudaGetSymbolAddress((void**)&pwinl, g_winl);
    cudaGetSymbolAddress((void**)&pwouth,g_wouth);
    cudaGetSymbolAddress((void**)&pwoutl,g_woutl);
    cudaGetSymbolAddress((void**)&pxnh,  g_xnh);
    cudaGetSymbolAddress((void**)&pyh,   g_yh);

    cudaFuncSetAttribute(hgemm_ps_kernel<0, 128>,
                         cudaFuncAttributeMaxDynamicSharedMemorySize, kSmem128);
    cudaFuncSetAttribute(hgemm_ps_kernel<1, 64>,
                         cudaFuncAttributeMaxDynamicSharedMemorySize, kSmem64);

    const int sBlocks = kScanT / 128;             // 768
    const int p2Blocks = (kB * kDI * kDS) / 128;  // 384

    // launch 0: embed, 1: split_in, 2: rmsnorm(L0), 3: in_proj <- ncu capture
    {
        int total = kRows * kD / 4;
        embed_kernel<<<(total + 255) / 256, 256>>>(input_ids, embed, px);
    }
    {
        int n4 = kInWN / 4;
        split_f32_kernel<<<(n4 + 255) / 256, 256>>>(in_proj_w, pwinh, pwinl, n4);
    }

    for (int l = 0; l < kNL; l++) {
        const float* w_norm = norm_w    + (size_t)l * kD;
        const float* w_cw   = conv_w    + (size_t)l * kDI * kDC;
        const float* w_cb   = conv_b    + (size_t)l * kDI;
        const float* w_xp   = x_proj_w  + (size_t)l * kDBC * kDI;
        const float* w_dtw  = dt_proj_w + (size_t)l * kDI * kDTR;
        const float* w_dtb  = dt_proj_b + (size_t)l * kDI;
        const float* w_Al   = A_log     + (size_t)l * kDI * kDS;
        const float* w_Dsk  = D_skip    + (size_t)l * kDI;
        const __nv_bfloat16* w_inh  = pwinh  + (size_t)l * 2 * kDI * kD;
        const __nv_bfloat16* w_inl  = pwinl  + (size_t)l * 2 * kDI * kD;
        const __nv_bfloat16* w_outh = pwouth + (size_t)l * kD * kDI;
        const __nv_bfloat16* w_outl = pwoutl + (size_t)l * kD * kDI;

        // rmsnorm -> bf16 hi plane
        rmsnorm_kernel<true><<<kRows, 192>>>(px, w_norm, nullptr, pxnh);

        // in_proj: pre-split 2-term, 128x128 tiles, 3-stage pipeline
        {
            dim3 grid(2 * kDI / 128, kRows / 128);   // (24,16)
            hgemm_ps_kernel<0, 128><<<grid, 256, kSmem128>>>(
                pxnh, w_inh, w_inl, pxz, 2 * kDI, kD);
        }

        // conv + silu (float4)
        {
            int total = kRows * kDI / 4;
            conv_silu_kernel<<<(total + 255) / 256, 256>>>(pxz, w_cw, w_cb, pxc);
        }

        // x_proj split-K
        {
            dim3 grid(2, kRows / 64, kXPChunks);
            gemm_xproj_splitk<<<grid, 256>>>(pxc, w_xp, pdbp);
            int total = kRows * kDBC;
            reduce_dbc_kernel<<<(total + 255) / 256, 256>>>(pdbp, pdbc);
        }

        // dt (fp32, K=48): BM=64 -> 384 blocks for better balance
        {
            dim3 grid(kDI / 128, kRows / 64);        // (12,32)
            sgemm_tn_kernel<2, 64><<<grid, 256>>>(pdbc, kDBC, w_dtw, pdt, kDI,
                                                  w_dtb, kRows, kDI, kDTR);
        }

        // chunked selective scan (register-state, 128-thread blocks)
        scan_p1<<<sBlocks, 128>>>(pdt, pxc, pdbc, w_Al, pE, pU);
        scan_p2<<<p2Blocks, 128>>>(pE, pU, pH);
        scan_p3<<<sBlocks, 128>>>(pdt, pxc, pdbc, pxz, w_Al, w_Dsk, pH, pyh);

        // split out_proj weights once, before first use
        if (l == 0) {
            int n4 = kOutWN / 4;
            split_f32_kernel<<<(n4 + 255) / 256, 256>>>(out_proj_w, pwouth, pwoutl, n4);
        }

        // out_proj + residual: pre-split 2-term, 64x128 tiles, 3-stage pipeline
        {
            dim3 grid(kD / 128, kRows / 64);         // (6,32)
            hgemm_ps_kernel<1, 64><<<grid, 256, kSmem64>>>(
                pyh, w_outh, w_outl, px, kD, kDI);
        }
    }

    rmsnorm_kernel<false><<<kRows, 192>>>(px, norm_f_w, pxn, nullptr);
    head_kernel<<<kB, 256>>>(pxn, cls_w, cls_b, out);
}

// round 16
// speedup vs baseline: 1.5711x; 1.1571x over previous
#include <cuda_runtime.h>
#include <cuda_bf16.h>
#include <cuda_fp16.h>
#include <math.h>
#include <stdint.h>

// ---------------- problem constants ----------------
constexpr int kV   = 50280;
constexpr int kD   = 768;
constexpr int kNL  = 8;
constexpr int kDI  = 1536;
constexpr int kDS  = 16;
constexpr int kDC  = 4;
constexpr int kDTR = 48;
constexpr int kNC  = 4;
constexpr int kB   = 2;
constexpr int kL   = 1024;
constexpr int kDBC = kDTR + 2 * kDS;  // 80
constexpr float kEPS = 1e-5f;

constexpr int kRows = kB * kL;        // 2048
constexpr int kXPChunks = 8;
constexpr int kXPKC = kDI / kXPChunks; // 192

// chunked scan
constexpr int kG   = 32;
constexpr int kNCH = kL / kG;         // 32
constexpr int kScanN = kB * kNCH * kDI * kDS;   // 1.57M
constexpr int kScanT = kB * kNCH * kDI;         // 98304 threads

constexpr int kInWN  = kNL * 2 * kDI * kD;   // 18.9M
constexpr int kOutWN = kNL * kD * kDI;       // 9.4M

// ---------------- device scratch ----------------
__device__ float g_x  [kRows * kD];
__device__ float g_xn [kRows * kD];          // fp32 (final norm only)
__device__ float g_xz [kRows * 2 * kDI];
__device__ float g_xc [kRows * kDI];
__device__ float g_dbc[kRows * kDBC];
__device__ float g_dbp[kXPChunks * kRows * kDBC];
__device__ float g_dt [kRows * kDI];
__device__ float g_E  [kScanN];
__device__ float g_U  [kScanN];
__device__ float g_H  [kScanN];

__device__ __align__(16) __half g_winh[kInWN];
__device__ __align__(16) __half g_wouth[kOutWN];
__device__ __align__(16) __half g_xnh[kRows * kD];
__device__ __align__(16) __half g_yh [kRows * kDI];

// ---------------- helpers ----------------
__device__ __forceinline__ float warp_sum(float v) {
#pragma unroll
    for (int o = 16; o > 0; o >>= 1) v += __shfl_xor_sync(0xffffffffu, v, o);
    return v;
}
__device__ __forceinline__ uint32_t smem_u32(const void* p) {
    return (uint32_t)__cvta_generic_to_shared(p);
}
__device__ __forceinline__ void ldmat_x4(uint32_t& r0, uint32_t& r1,
                                         uint32_t& r2, uint32_t& r3,
                                         uint32_t addr) {
    asm volatile("ldmatrix.sync.aligned.m8n8.x4.shared.b16 {%0,%1,%2,%3}, [%4];"
                 : "=r"(r0), "=r"(r1), "=r"(r2), "=r"(r3) : "r"(addr));
}
__device__ __forceinline__ void mma16816h(float* c, const uint32_t* a,
                                          uint32_t b0, uint32_t b1) {
    asm volatile(
        "mma.sync.aligned.m16n8k16.row.col.f32.f16.f16.f32 "
        "{%0,%1,%2,%3}, {%4,%5,%6,%7}, {%8,%9}, {%0,%1,%2,%3};"
        : "+f"(c[0]), "+f"(c[1]), "+f"(c[2]), "+f"(c[3])
        : "r"(a[0]), "r"(a[1]), "r"(a[2]), "r"(a[3]), "r"(b0), "r"(b1));
}
__device__ __forceinline__ void cp16(uint32_t dst, const void* src) {
    asm volatile("cp.async.cg.shared.global [%0], [%1], 16;\n" :: "r"(dst), "l"(src));
}
__device__ __forceinline__ void cp_commit() {
    asm volatile("cp.async.commit_group;\n");
}
template <int N>
__device__ __forceinline__ void cp_wait() {
    asm volatile("cp.async.wait_group %0;\n" :: "n"(N));
}

// ---------------- fp32 -> fp16 weight convert ----------------
__global__ void cvt_f16_kernel(const float* __restrict__ src,
                               __half* __restrict__ h, int n4) {
    int i = blockIdx.x * blockDim.x + threadIdx.x;
    if (i >= n4) return;
    float4 v = ((const float4*)src)[i];
    ((__half2*)h)[i * 2]     = __floats2half2_rn(v.x, v.y);
    ((__half2*)h)[i * 2 + 1] = __floats2half2_rn(v.z, v.w);
}

// ---------------- embed gather ----------------
__global__ void embed_kernel(const int* __restrict__ ids,
                             const float* __restrict__ embed,
                             float* __restrict__ x) {
    int idx = blockIdx.x * blockDim.x + threadIdx.x;
    int total = kRows * kD / 4;
    if (idx >= total) return;
    int row = idx / (kD / 4);
    int d4 = idx - row * (kD / 4);
    const float4* src = (const float4*)(embed + (size_t)ids[row] * kD);
    ((float4*)x)[idx] = src[d4];
}

// ---------------- rmsnorm (float4): SPLIT -> fp16 plane; else fp32 ----------
template <bool SPLIT>
__global__ void rmsnorm_kernel(const float* __restrict__ x,
                               const float* __restrict__ w,
                               float* __restrict__ outf,
                               __half* __restrict__ outh) {
    int row = blockIdx.x;
    const float4* xr = (const float4*)(x + (size_t)row * kD);
    float s = 0.f;
    for (int d4 = threadIdx.x; d4 < kD / 4; d4 += blockDim.x) {
        float4 v = xr[d4];
        s = fmaf(v.x, v.x, s);
        s = fmaf(v.y, v.y, s);
        s = fmaf(v.z, v.z, s);
        s = fmaf(v.w, v.w, s);
    }
    s = warp_sum(s);
    __shared__ float sh[8];
    __shared__ float inv_s;
    int wid = threadIdx.x >> 5, lane = threadIdx.x & 31;
    if (lane == 0) sh[wid] = s;
    __syncthreads();
    if (wid == 0) {
        float t = (lane < (blockDim.x >> 5)) ? sh[lane] : 0.f;
        t = warp_sum(t);
        if (lane == 0) inv_s = rsqrtf(t / (float)kD + kEPS);
    }
    __syncthreads();
    float inv = inv_s;
    const float4* wr = (const float4*)w;
    for (int d4 = threadIdx.x; d4 < kD / 4; d4 += blockDim.x) {
        float4 v = xr[d4];
        float4 ww = wr[d4];
        v.x = v.x * inv * ww.x;
        v.y = v.y * inv * ww.y;
        v.z = v.z * inv * ww.z;
        v.w = v.w * inv * ww.w;
        if (SPLIT) {
            __half2* o = (__half2*)(outh + (size_t)row * kD + d4 * 4);
            o[0] = __floats2half2_rn(v.x, v.y);
            o[1] = __floats2half2_rn(v.z, v.w);
        } else {
            ((float4*)(outf + (size_t)row * kD))[d4] = v;
        }
    }
}

// =====================================================================
// fp16 tensor-core GEMM, 3-stage cp.async, single sync/kt, 1 MMA term.
//   C[M,N] = A[M,K] @ Bw[N,K]^T     (A, Bw in fp16)
//   BM in {64,128}, BN=128, BK=32, 256 threads (8 warps: 2 in M, 4 in N)
// EPI 0: store    EPI 1: C += result
// =====================================================================
template <int EPI, int BM>
__global__ __launch_bounds__(256, 2)
void hgemm_ps_kernel(const __half* __restrict__ Ah,
                     const __half* __restrict__ Bh,
                     float* __restrict__ C, int ldc, int K) {
    constexpr int BN = 128, BK = 32;
    constexpr int STR = 40;
    constexpr int WM = BM / 2;
    constexpr int MF = WM / 16;
    constexpr int ASZ = BM * STR;
    constexpr int BSZ = BN * STR;
    constexpr int ACH = BM / 64;
    constexpr int ST = 3;

    extern __shared__ __half sm[];
    __half* As_h = sm;                    // [ST][ASZ]
    __half* Bs_h = As_h + ST * ASZ;       // [ST][BSZ]

    const int tid = threadIdx.x;
    const int wid = tid >> 5, lane = tid & 31;
    const int bm0 = blockIdx.y * BM;
    const int bn0 = blockIdx.x * BN;
    const int wm = wid & 1;
    const int wn = wid >> 1;

    float acc[MF][4][4];
#pragma unroll
    for (int i = 0; i < MF; i++)
#pragma unroll
        for (int j = 0; j < 4; j++)
#pragma unroll
            for (int v = 0; v < 4; v++) acc[i][j][v] = 0.f;

    auto issue_loads = [&](int buf, int k0) {
#pragma unroll
        for (int u = 0; u < ACH; u++) {
            int id = tid + u * 256;
            int r = id >> 2, c8 = (id & 3) * 8;
            size_t g = (size_t)(bm0 + r) * K + k0 + c8;
            cp16(smem_u32(As_h + buf * ASZ + r * STR + c8), Ah + g);
        }
#pragma unroll
        for (int u = 0; u < 2; u++) {
            int id = tid + u * 256;
            int r = id >> 2, c8 = (id & 3) * 8;
            size_t g = (size_t)(bn0 + r) * K + k0 + c8;
            cp16(smem_u32(Bs_h + buf * BSZ + r * STR + c8), Bh + g);
        }
    };

    const int a_row = wm * WM + (lane & 15);
    const int a_col8 = (lane >> 4) << 3;
    const int b_grp = lane >> 3;
    const int b_row = wn * 32 + ((b_grp >> 1) << 3) + (lane & 7);
    const int b_col8 = (b_grp & 1) << 3;

    const int KT = K / BK;
    issue_loads(0, 0);
    cp_commit();
    if (KT > 1) { issue_loads(1, BK); cp_commit(); }

    for (int kt = 0; kt < KT; kt++) {
        if (kt + 1 < KT) cp_wait<1>(); else cp_wait<0>();
        __syncthreads();
        if (kt + 2 < KT) {
            issue_loads((kt + 2) % ST, (kt + 2) * BK);
            cp_commit();
        }
        const int buf = kt % ST;

#pragma unroll
        for (int kk = 0; kk < 2; kk++) {
            uint32_t ah[MF][4];
            uint32_t bh[4][2];
#pragma unroll
            for (int i = 0; i < MF; i++) {
                uint32_t off = (uint32_t)(buf * ASZ + (a_row + i * 16) * STR
                                          + kk * 16 + a_col8);
                ldmat_x4(ah[i][0], ah[i][1], ah[i][2], ah[i][3],
                         smem_u32(As_h + off));
            }
#pragma unroll
            for (int jj = 0; jj < 2; jj++) {
                uint32_t off = (uint32_t)(buf * BSZ + (b_row + jj * 16) * STR
                                          + kk * 16 + b_col8);
                ldmat_x4(bh[jj * 2][0], bh[jj * 2][1],
                         bh[jj * 2 + 1][0], bh[jj * 2 + 1][1],
                         smem_u32(Bs_h + off));
            }
#pragma unroll
            for (int i = 0; i < MF; i++)
#pragma unroll
                for (int j = 0; j < 4; j++)
                    mma16816h(acc[i][j], ah[i], bh[j][0], bh[j][1]);
        }
    }

    const int c_row = bm0 + wm * WM + (lane >> 2);
    const int c_col = bn0 + wn * 32 + (lane & 3) * 2;
#pragma unroll
    for (int i = 0; i < MF; i++) {
#pragma unroll
        for (int j = 0; j < 4; j++) {
#pragma unroll
            for (int half = 0; half < 2; half++) {
                int gm = c_row + i * 16 + half * 8;
                int gn = c_col + j * 8;
                float* cp = C + (size_t)gm * ldc + gn;
                float v0 = acc[i][j][half * 2 + 0];
                float v1 = acc[i][j][half * 2 + 1];
                if (EPI == 1) {
                    float2 old = *(const float2*)cp;
                    v0 += old.x; v1 += old.y;
                }
                *(float2*)cp = make_float2(v0, v1);
            }
        }
    }
}

constexpr int kSmem128 = 3 * (128 * 40 + 128 * 40) * 2;  // 61440
constexpr int kSmem64  = 3 * (64 * 40 + 128 * 40) * 2;   // 46080

// =====================================================================
// fp32 GEMM (dt_proj, K=48)
// =====================================================================
template <int EPI, int BMt>
__global__ __launch_bounds__(256)
void sgemm_tn_kernel(const float* __restrict__ A, int lda,
                     const float* __restrict__ Bw,
                     float* __restrict__ C, int ldc,
                     const float* __restrict__ bias,
                     int M, int N, int K) {
    constexpr int BN = 128, BK = 8;
    constexpr int MR = BMt / 16;
    constexpr int AE = BMt * BK / 256;
    __shared__ float As[2][BK][BMt + 4];
    __shared__ float Bs[2][BK][BN + 4];

    const int tid = threadIdx.x;
    const int bm0 = blockIdx.y * BMt;
    const int bn0 = blockIdx.x * BN;
    const int tx = tid & 15;
    const int ty = tid >> 4;

    const int blr = tid >> 1;
    const int bk4 = (tid & 1) * 4;
    const int gnb = bn0 + blr;
    const bool bvalid = (gnb < N);
    const float* Bbase = Bw + (size_t)gnb * K + bk4;

    float aR[AE];
    float4 bR;

#pragma unroll
    for (int u = 0; u < AE; u++) {
        int e = tid + u * 256;
        int r = e >> 3, k = e & 7;
        aR[u] = A[(size_t)(bm0 + r) * lda + k];
    }
    bR = bvalid ? *(const float4*)Bbase : make_float4(0.f, 0.f, 0.f, 0.f);
#pragma unroll
    for (int u = 0; u < AE; u++) {
        int e = tid + u * 256;
        As[0][e & 7][e >> 3] = aR[u];
    }
    Bs[0][bk4 + 0][blr] = bR.x;
    Bs[0][bk4 + 1][blr] = bR.y;
    Bs[0][bk4 + 2][blr] = bR.z;
    Bs[0][bk4 + 3][blr] = bR.w;
    __syncthreads();

    float acc[MR][8];
#pragma unroll
    for (int i = 0; i < MR; i++)
#pragma unroll
        for (int j = 0; j < 8; j++) acc[i][j] = 0.f;

    const int KT = K / BK;
    int buf = 0;
    for (int kt = 0; kt < KT; kt++) {
        if (kt + 1 < KT) {
            const int k0 = (kt + 1) * BK;
#pragma unroll
            for (int u = 0; u < AE; u++) {
                int e = tid + u * 256;
                int r = e >> 3, k = e & 7;
                aR[u] = A[(size_t)(bm0 + r) * lda + k0 + k];
            }
            bR = bvalid ? *(const float4*)(Bbase + k0) : make_float4(0.f, 0.f, 0.f, 0.f);
        }
#pragma unroll
        for (int k = 0; k < BK; k++) {
            float a[MR], b[8];
            {
                float4 a0 = *(const float4*)&As[buf][k][ty * 4];
                a[0] = a0.x; a[1] = a0.y; a[2] = a0.z; a[3] = a0.w;
                if (MR == 8) {
                    float4 a1 = *(const float4*)&As[buf][k][ty * 4 + 64];
                    a[4] = a1.x; a[5] = a1.y; a[6] = a1.z; a[7] = a1.w;
                }
                float4 b0 = *(const float4*)&Bs[buf][k][tx * 4];
                float4 b1 = *(const float4*)&Bs[buf][k][tx * 4 + 64];
                b[0] = b0.x; b[1] = b0.y; b[2] = b0.z; b[3] = b0.w;
                b[4] = b1.x; b[5] = b1.y; b[6] = b1.z; b[7] = b1.w;
            }
#pragma unroll
            for (int i = 0; i < MR; i++)
#pragma unroll
                for (int j = 0; j < 8; j++)
                    acc[i][j] = fmaf(a[i], b[j], acc[i][j]);
        }
        if (kt + 1 < KT) {
            int nb = buf ^ 1;
#pragma unroll
            for (int u = 0; u < AE; u++) {
                int e = tid + u * 256;
                As[nb][e & 7][e >> 3] = aR[u];
            }
            Bs[nb][bk4 + 0][blr] = bR.x;
            Bs[nb][bk4 + 1][blr] = bR.y;
            Bs[nb][bk4 + 2][blr] = bR.z;
            Bs[nb][bk4 + 3][blr] = bR.w;
            __syncthreads();
            buf = nb;
        }
    }

#pragma unroll
    for (int i = 0; i < MR; i++) {
        int gm = bm0 + ty * 4 + (i & 3) + (i >> 2) * 64;
#pragma unroll
        for (int jj = 0; jj < 2; jj++) {
            int gn = bn0 + tx * 4 + jj * 64;
            if (gn >= N) continue;
            float v0 = acc[i][jj * 4 + 0];
            float v1 = acc[i][jj * 4 + 1];
            float v2 = acc[i][jj * 4 + 2];
            float v3 = acc[i][jj * 4 + 3];
            float* cp = C + (size_t)gm * ldc + gn;
            if (EPI == 1) {
                float4 old = *(const float4*)cp;
                v0 += old.x; v1 += old.y; v2 += old.z; v3 += old.w;
            }
            if (EPI == 2) {
                float bb[4] = {bias[gn], bias[gn + 1], bias[gn + 2], bias[gn + 3]};
                v0 += bb[0]; v1 += bb[1]; v2 += bb[2]; v3 += bb[3];
                v0 = fmaxf(v0, 0.f) + log1pf(expf(-fabsf(v0)));
                v1 = fmaxf(v1, 0.f) + log1pf(expf(-fabsf(v1)));
                v2 = fmaxf(v2, 0.f) + log1pf(expf(-fabsf(v2)));
                v3 = fmaxf(v3, 0.f) + log1pf(expf(-fabsf(v3)));
            }
            *(float4*)cp = make_float4(v0, v1, v2, v3);
        }
    }
}

// =====================================================================
// x_proj split-K GEMM + reduce
// =====================================================================
__global__ void gemm_xproj_splitk(const float* __restrict__ A,
                                  const float* __restrict__ Bw,
                                  float* __restrict__ part) {
    constexpr int BM = 64, BN = 64, BK = 16;
    __shared__ float As[BK][BM + 4];
    __shared__ float Bs[BK][BN + 4];
    const int tid = threadIdx.x;
    const int bm0 = blockIdx.y * BM;
    const int bn0 = blockIdx.x * BN;
    const int zoff = blockIdx.z * kXPKC;
    const int tx = tid & 15;
    const int ty = tid >> 4;
    float acc[4][4] = {};

    for (int k0 = 0; k0 < kXPKC; k0 += BK) {
#pragma unroll
        for (int t = tid; t < BM * BK; t += 256) {
            int m = t >> 4, k = t & 15;
            As[k][m] = A[(size_t)(bm0 + m) * kDI + zoff + k0 + k];
        }
#pragma unroll
        for (int t = tid; t < BN * BK; t += 256) {
            int n = t >> 4, k = t & 15;
            int gn = bn0 + n;
            Bs[k][n] = (gn < kDBC) ? Bw[(size_t)gn * kDI + zoff + k0 + k] : 0.f;
        }
        __syncthreads();
#pragma unroll
        for (int k = 0; k < BK; k++) {
            float a[4], b[4];
#pragma unroll
            for (int i = 0; i < 4; i++) a[i] = As[k][ty * 4 + i];
#pragma unroll
            for (int j = 0; j < 4; j++) b[j] = Bs[k][tx * 4 + j];
#pragma unroll
            for (int i = 0; i < 4; i++)
#pragma unroll
                for (int j = 0; j < 4; j++)
                    acc[i][j] = fmaf(a[i], b[j], acc[i][j]);
        }
        __syncthreads();
    }

    float* base = part + (size_t)blockIdx.z * kRows * kDBC;
#pragma unroll
    for (int i = 0; i < 4; i++) {
        int gm = bm0 + ty * 4 + i;
#pragma unroll
        for (int j = 0; j < 4; j++) {
            int gn = bn0 + tx * 4 + j;
            if (gn < kDBC) base[(size_t)gm * kDBC + gn] = acc[i][j];
        }
    }
}

__global__ void reduce_dbc_kernel(const float* __restrict__ part,
                                  float* __restrict__ dbc) {
    int idx = blockIdx.x * blockDim.x + threadIdx.x;
    if (idx >= kRows * kDBC) return;
    float s = 0.f;
#pragma unroll
    for (int z = 0; z < kXPChunks; z++)
        s += part[(size_t)z * kRows * kDBC + idx];
    dbc[idx] = s;
}

// ---------------- causal depthwise conv (DC=4) + SiLU, float4 ----------------
__global__ void conv_silu_kernel(const float* __restrict__ xz,
                                 const float* __restrict__ cw,
                                 const float* __restrict__ cb,
                                 float* __restrict__ xc) {
    int idx = blockIdx.x * blockDim.x + threadIdx.x;
    int total = kRows * kDI / 4;
    if (idx >= total) return;
    int i4 = idx % (kDI / 4);
    int r = idx / (kDI / 4);
    int l = r % kL;
    int b = r / kL;
    int i = i4 * 4;

    float4 acc = *(const float4*)(cb + i);
#pragma unroll
    for (int k = 0; k < kDC; k++) {
        int ls = l + k - (kDC - 1);
        if (ls >= 0) {
            const float4 xv = *(const float4*)(xz + ((size_t)(b * kL + ls)) * (2 * kDI) + i);
            acc.x = fmaf(xv.x, cw[(i + 0) * kDC + k], acc.x);
            acc.y = fmaf(xv.y, cw[(i + 1) * kDC + k], acc.y);
            acc.z = fmaf(xv.z, cw[(i + 2) * kDC + k], acc.z);
            acc.w = fmaf(xv.w, cw[(i + 3) * kDC + k], acc.w);
        }
    }
    acc.x = acc.x / (1.f + __expf(-acc.x));
    acc.y = acc.y / (1.f + __expf(-acc.y));
    acc.z = acc.z / (1.f + __expf(-acc.z));
    acc.w = acc.w / (1.f + __expf(-acc.w));
    *(float4*)(xc + (size_t)r * kDI + i) = acc;
}

// =====================================================================
// chunked selective scan — register-state version (128-thread blocks)
// =====================================================================
__global__ __launch_bounds__(128)
void scan_p1(const float* __restrict__ dt,
             const float* __restrict__ xc,
             const float* __restrict__ dbc,
             const float* __restrict__ A_log,
             float* __restrict__ E, float* __restrict__ U) {
    int n = blockIdx.x * blockDim.x + threadIdx.x;
    if (n >= kScanT) return;
    int i = n % kDI;
    int bc = n / kDI;
    int c = bc & (kNCH - 1);
    int b = bc >> 5;

    float a[kDS];
#pragma unroll
    for (int q = 0; q < 4; q++) {
        float4 v = *(const float4*)(A_log + (size_t)i * kDS + q * 4);
        a[q * 4 + 0] = -__expf(v.x);
        a[q * 4 + 1] = -__expf(v.y);
        a[q * 4 + 2] = -__expf(v.z);
        a[q * 4 + 3] = -__expf(v.w);
    }
    float h[kDS], Ep[kDS];
#pragma unroll
    for (int s = 0; s < kDS; s++) { h[s] = 0.f; Ep[s] = 1.f; }

    size_t r0 = (size_t)b * kL + c * kG;
    const float* pdt = dt + r0 * kDI + i;
    const float* pxc = xc + r0 * kDI + i;
    const float* pB  = dbc + r0 * kDBC + kDTR;
    for (int g = 0; g < kG; g++) {
        float dt_t = *pdt, x_t = *pxc;
        float Bv[kDS];
#pragma unroll
        for (int q = 0; q < 4; q++) {
            float4 v = *(const float4*)(pB + q * 4);
            Bv[q * 4 + 0] = v.x; Bv[q * 4 + 1] = v.y;
            Bv[q * 4 + 2] = v.z; Bv[q * 4 + 3] = v.w;
        }
#pragma unroll
        for (int s = 0; s < kDS; s++) {
            float e = __expf(dt_t * a[s]);
            h[s] = fmaf(h[s], e, dt_t * x_t * Bv[s]);
            Ep[s] *= e;
        }
        pdt += kDI; pxc += kDI; pB += kDBC;
    }
    size_t t0 = (size_t)n * kDS;
#pragma unroll
    for (int q = 0; q < 4; q++) {
        *(float4*)(E + t0 + q * 4) = make_float4(Ep[q * 4], Ep[q * 4 + 1],
                                                 Ep[q * 4 + 2], Ep[q * 4 + 3]);
        *(float4*)(U + t0 + q * 4) = make_float4(h[q * 4], h[q * 4 + 1],
                                                 h[q * 4 + 2], h[q * 4 + 3]);
    }
}

__global__ __launch_bounds__(128)
void scan_p2(const float* __restrict__ E,
             const float* __restrict__ U,
             float* __restrict__ H) {
    int t = blockIdx.x * blockDim.x + threadIdx.x;
    int sb = t >> 4;
    int s = t & 15;
    int i = sb % kDI;
    int b = sb / kDI;
    float h = 0.f;
#pragma unroll
    for (int c = 0; c < kNCH; c++) {
        size_t idx = ((((size_t)b * kNCH + c) * kDI + i) << 4) + s;
        H[idx] = h;
        h = fmaf(E[idx], h, U[idx]);
    }
}

__global__ __launch_bounds__(128)
void scan_p3(const float* __restrict__ dt,
             const float* __restrict__ xc,
             const float* __restrict__ dbc,
             const float* __restrict__ xz,
             const float* __restrict__ A_log,
             const float* __restrict__ D_skip,
             const float* __restrict__ H,
             __half* __restrict__ yh) {
    int n = blockIdx.x * blockDim.x + threadIdx.x;
    if (n >= kScanT) return;
    int i = n % kDI;
    int bc = n / kDI;
    int c = bc & (kNCH - 1);
    int b = bc >> 5;

    float a[kDS];
#pragma unroll
    for (int q = 0; q < 4; q++) {
        float4 v = *(const float4*)(A_log + (size_t)i * kDS + q * 4);
        a[q * 4 + 0] = -__expf(v.x);
        a[q * 4 + 1] = -__expf(v.y);
        a[q * 4 + 2] = -__expf(v.z);
        a[q * 4 + 3] = -__expf(v.w);
    }
    const float dsk = D_skip[i];
    float h[kDS];
    size_t t0 = (size_t)n * kDS;
#pragma unroll
    for (int q = 0; q < 4; q++) {
        float4 v = *(const float4*)(H + t0 + q * 4);
        h[q * 4 + 0] = v.x; h[q * 4 + 1] = v.y;
        h[q * 4 + 2] = v.z; h[q * 4 + 3] = v.w;
    }

    size_t r0 = (size_t)b * kL + c * kG;
    const float* pdt = dt + r0 * kDI + i;
    const float* pxc = xc + r0 * kDI + i;
    const float* pB  = dbc + r0 * kDBC + kDTR;
    const float* pC  = dbc + r0 * kDBC + kDTR + kDS;
    const float* pz  = xz + r0 * (2 * kDI) + kDI + i;
    __half* pyh = yh + r0 * kDI + i;
    for (int g = 0; g < kG; g++) {
        float dt_t = *pdt, x_t = *pxc;
        float Bv[kDS], Cv[kDS];
#pragma unroll
        for (int q = 0; q < 4; q++) {
            float4 v = *(const float4*)(pB + q * 4);
            Bv[q * 4 + 0] = v.x; Bv[q * 4 + 1] = v.y;
            Bv[q * 4 + 2] = v.z; Bv[q * 4 + 3] = v.w;
            float4 w = *(const float4*)(pC + q * 4);
            Cv[q * 4 + 0] = w.x; Cv[q * 4 + 1] = w.y;
            Cv[q * 4 + 2] = w.z; Cv[q * 4 + 3] = w.w;
        }
        float tmp[kDS];
#pragma unroll
        for (int s = 0; s < kDS; s++) {
            float e = __expf(dt_t * a[s]);
            h[s] = fmaf(h[s], e, dt_t * x_t * Bv[s]);
            tmp[s] = h[s] * Cv[s];
        }
#pragma unroll
        for (int st = 8; st > 0; st >>= 1)
#pragma unroll
            for (int s = 0; s < st; s++) tmp[s] += tmp[s + st];
        float z = *pz;
        float yy = fmaf(x_t, dsk, tmp[0]);
        yy *= z / (1.f + __expf(-z));
        *pyh = __float2half_rn(yy);

        pdt += kDI; pxc += kDI; pB += kDBC; pC += kDBC;
        pz += 2 * kDI; pyh += kDI;
    }
}

// ---------------- final head ----------------
__global__ void head_kernel(const float* __restrict__ xn,
                            const float* __restrict__ cls_w,
                            const float* __restrict__ cls_b,
                            float* __restrict__ out) {
    int b = blockIdx.x;
    __shared__ float mean[kD];
    for (int d = threadIdx.x; d < kD; d += blockDim.x) {
        float s = 0.f;
        const float* p = xn + ((size_t)b * kL) * kD + d;
        for (int l = 0; l < kL; l++) s += p[(size_t)l * kD];
        mean[d] = s / (float)kL;
    }
    __syncthreads();
    if (threadIdx.x < kNC) {
        int c = threadIdx.x;
        float s = cls_b[c];
        for (int d = 0; d < kD; d++) s = fmaf(mean[d], cls_w[c * kD + d], s);
        out[b * kNC + c] = s;
    }
}

// ---------------- launch ----------------
extern "C" void kernel_launch(void* const* d_in, const int* in_sizes, int n_in,
                              void* d_out, int out_size) {
    const int*   input_ids = (const int*)  d_in[0];
    const float* embed     = (const float*)d_in[1];
    const float* norm_w    = (const float*)d_in[2];
    const float* in_proj_w = (const float*)d_in[3];
    const float* conv_w    = (const float*)d_in[4];
    const float* conv_b    = (const float*)d_in[5];
    const float* x_proj_w  = (const float*)d_in[6];
    const float* dt_proj_w = (const float*)d_in[7];
    const float* dt_proj_b = (const float*)d_in[8];
    const float* A_log     = (const float*)d_in[9];
    const float* D_skip    = (const float*)d_in[10];
    const float* out_proj_w= (const float*)d_in[11];
    const float* norm_f_w  = (const float*)d_in[12];
    const float* cls_w     = (const float*)d_in[13];
    const float* cls_b     = (const float*)d_in[14];
    float* out = (float*)d_out;

    float *px, *pxn, *pxz, *pxc, *pdbc, *pdbp, *pdt, *pE, *pU, *pH;
    __half *pwinh, *pwouth, *pxnh, *pyh;
    cudaGetSymbolAddress((void**)&px,    g_x);
    cudaGetSymbolAddress((void**)&pxn,   g_xn);
    cudaGetSymbolAddress((void**)&pxz,   g_xz);
    cudaGetSymbolAddress((void**)&pxc,   g_xc);
    cudaGetSymbolAddress((void**)&pdbc,  g_dbc);
    cudaGetSymbolAddress((void**)&pdbp,  g_dbp);
    cudaGetSymbolAddress((void**)&pdt,   g_dt);
    cudaGetSymbolAddress((void**)&pE,    g_E);
    cudaGetSymbolAddress((void**)&pU,    g_U);
    cudaGetSymbolAddress((void**)&pH,    g_H);
    cudaGetSymbolAddress((void**)&pwinh, g_winh);
    cudaGetSymbolAddress((void**)&pwouth,g_wouth);
    cudaGetSymbolAddress((void**)&pxnh,  g_xnh);
    cudaGetSymbolAddress((void**)&pyh,   g_yh);

    cudaFuncSetAttribute(hgemm_ps_kernel<0, 128>,
                         cudaFuncAttributeMaxDynamicSharedMemorySize, kSmem128);
    cudaFuncSetAttribute(hgemm_ps_kernel<1, 64>,
                         cudaFuncAttributeMaxDynamicSharedMemorySize, kSmem64);

    const int sBlocks = kScanT / 128;             // 768
    const int p2Blocks = (kB * kDI * kDS) / 128;  // 384

    // launch 0: embed, 1: cvt_in, 2: rmsnorm(L0), 3: in_proj <- ncu capture
    {
        int total = kRows * kD / 4;
        embed_kernel<<<(total + 255) / 256, 256>>>(input_ids, embed, px);
    }
    {
        int n4 = kInWN / 4;
        cvt_f16_kernel<<<(n4 + 255) / 256, 256>>>(in_proj_w, pwinh, n4);
    }

    for (int l = 0; l < kNL; l++) {
        const float* w_norm = norm_w    + (size_t)l * kD;
        const float* w_cw   = conv_w    + (size_t)l * kDI * kDC;
        const float* w_cb   = conv_b    + (size_t)l * kDI;
        const float* w_xp   = x_proj_w  + (size_t)l * kDBC * kDI;
        const float* w_dtw  = dt_proj_w + (size_t)l * kDI * kDTR;
        const float* w_dtb  = dt_proj_b + (size_t)l * kDI;
        const float* w_Al   = A_log     + (size_t)l * kDI * kDS;
        const float* w_Dsk  = D_skip    + (size_t)l * kDI;
        const __half* w_inh  = pwinh  + (size_t)l * 2 * kDI * kD;
        const __half* w_outh = pwouth + (size_t)l * kD * kDI;

        // rmsnorm -> fp16 plane
        rmsnorm_kernel<true><<<kRows, 192>>>(px, w_norm, nullptr, pxnh);

        // in_proj: fp16 single-term, 128x128 tiles, 3-stage pipeline
        {
            dim3 grid(2 * kDI / 128, kRows / 128);   // (24,16)
            hgemm_ps_kernel<0, 128><<<grid, 256, kSmem128>>>(
                pxnh, w_inh, pxz, 2 * kDI, kD);
        }

        // conv + silu (float4)
        {
            int total = kRows * kDI / 4;
            conv_silu_kernel<<<(total + 255) / 256, 256>>>(pxz, w_cw, w_cb, pxc);
        }

        // x_proj split-K
        {
            dim3 grid(2, kRows / 64, kXPChunks);
            gemm_xproj_splitk<<<grid, 256>>>(pxc, w_xp, pdbp);
            int total = kRows * kDBC;
            reduce_dbc_kernel<<<(total + 255) / 256, 256>>>(pdbp, pdbc);
        }

        // dt (fp32, K=48): BM=64 -> 384 blocks
        {
            dim3 grid(kDI / 128, kRows / 64);        // (12,32)
            sgemm_tn_kernel<2, 64><<<grid, 256>>>(pdbc, kDBC, w_dtw, pdt, kDI,
                                                  w_dtb, kRows, kDI, kDTR);
        }

        // chunked selective scan (register-state, 128-thread blocks)
        scan_p1<<<sBlocks, 128>>>(pdt, pxc, pdbc, w_Al, pE, pU);
        scan_p2<<<p2Blocks, 128>>>(pE, pU, pH);
        scan_p3<<<sBlocks, 128>>>(pdt, pxc, pdbc, pxz, w_Al, w_Dsk, pH, pyh);

        // convert out_proj weights once, before first use
        if (l == 0) {
            int n4 = kOutWN / 4;
            cvt_f16_kernel<<<(n4 + 255) / 256, 256>>>(out_proj_w, pwouth, n4);
        }

        // out_proj + residual: fp16 single-term, 64x128 tiles
        {
            dim3 grid(kD / 128, kRows / 64);         // (6,32)
            hgemm_ps_kernel<1, 64><<<grid, 256, kSmem64>>>(
                pyh, w_outh, px, kD, kDI);
        }
    }

    rmsnorm_kernel<false><<<kRows, 192>>>(px, norm_f_w, pxn, nullptr);
    head_kernel<<<kB, 256>>>(pxn, cls_w, cls_b, out);
}

// round 17
// speedup vs baseline: 1.6120x; 1.0261x over previous
#include <cuda_runtime.h>
#include <cuda_bf16.h>
#include <cuda_fp16.h>
#include <math.h>
#include <stdint.h>

// ---------------- problem constants ----------------
constexpr int kV   = 50280;
constexpr int kD   = 768;
constexpr int kNL  = 8;
constexpr int kDI  = 1536;
constexpr int kDS  = 16;
constexpr int kDC  = 4;
constexpr int kDTR = 48;
constexpr int kDTRp= 64;              // padded K for fp16 dt GEMM
constexpr int kNC  = 4;
constexpr int kB   = 2;
constexpr int kL   = 1024;
constexpr int kDBC = kDTR + 2 * kDS;  // 80
constexpr float kEPS = 1e-5f;

constexpr int kRows = kB * kL;        // 2048
constexpr int kXPChunks = 8;
constexpr int kXPKC = kDI / kXPChunks; // 192

// chunked scan
constexpr int kG   = 32;
constexpr int kNCH = kL / kG;         // 32
constexpr int kScanN = kB * kNCH * kDI * kDS;   // 1.57M
constexpr int kScanT = kB * kNCH * kDI;         // 98304 threads

constexpr int kInWN  = kNL * 2 * kDI * kD;   // 18.9M
constexpr int kOutWN = kNL * kD * kDI;       // 9.4M

// ---------------- device scratch ----------------
__device__ float g_x  [kRows * kD];
__device__ float g_xn [kRows * kD];
__device__ float g_xz [kRows * 2 * kDI];
__device__ float g_xc [kRows * kDI];
__device__ float g_dbc[kRows * kDBC];
__device__ float g_dbp[kXPChunks * kRows * kDBC];
__device__ float g_dt [kRows * kDI];
__device__ float g_E  [kScanN];
__device__ float g_U  [kScanN];
__device__ float g_H  [kScanN];

__device__ __align__(16) __half g_winh[kInWN];
__device__ __align__(16) __half g_wouth[kOutWN];
__device__ __align__(16) __half g_xnh[kRows * kD];
__device__ __align__(16) __half g_yh [kRows * kDI];
// K-padded fp16 planes for dt GEMM; pad columns (48..63) are never written
// and stay zero from static initialization.
__device__ __align__(16) __half g_dtr [kRows * kDTRp];
__device__ __align__(16) __half g_dtwh[kNL * kDI * kDTRp];

// ---------------- helpers ----------------
__device__ __forceinline__ float warp_sum(float v) {
#pragma unroll
    for (int o = 16; o > 0; o >>= 1) v += __shfl_xor_sync(0xffffffffu, v, o);
    return v;
}
__device__ __forceinline__ uint32_t smem_u32(const void* p) {
    return (uint32_t)__cvta_generic_to_shared(p);
}
__device__ __forceinline__ void ldmat_x4(uint32_t& r0, uint32_t& r1,
                                         uint32_t& r2, uint32_t& r3,
                                         uint32_t addr) {
    asm volatile("ldmatrix.sync.aligned.m8n8.x4.shared.b16 {%0,%1,%2,%3}, [%4];"
                 : "=r"(r0), "=r"(r1), "=r"(r2), "=r"(r3) : "r"(addr));
}
__device__ __forceinline__ void mma16816h(float* c, const uint32_t* a,
                                          uint32_t b0, uint32_t b1) {
    asm volatile(
        "mma.sync.aligned.m16n8k16.row.col.f32.f16.f16.f32 "
        "{%0,%1,%2,%3}, {%4,%5,%6,%7}, {%8,%9}, {%0,%1,%2,%3};"
        : "+f"(c[0]), "+f"(c[1]), "+f"(c[2]), "+f"(c[3])
        : "r"(a[0]), "r"(a[1]), "r"(a[2]), "r"(a[3]), "r"(b0), "r"(b1));
}
__device__ __forceinline__ void cp16(uint32_t dst, const void* src) {
    asm volatile("cp.async.cg.shared.global [%0], [%1], 16;\n" :: "r"(dst), "l"(src));
}
__device__ __forceinline__ void cp_commit() {
    asm volatile("cp.async.commit_group;\n");
}
template <int N>
__device__ __forceinline__ void cp_wait() {
    asm volatile("cp.async.wait_group %0;\n" :: "n"(N));
}

// ---------------- weight converts ----------------
__global__ void cvt_f16_kernel(const float* __restrict__ src,
                               __half* __restrict__ h, int n4) {
    int i = blockIdx.x * blockDim.x + threadIdx.x;
    if (i >= n4) return;
    float4 v = ((const float4*)src)[i];
    ((__half2*)h)[i * 2]     = __floats2half2_rn(v.x, v.y);
    ((__half2*)h)[i * 2 + 1] = __floats2half2_rn(v.z, v.w);
}

// dt_proj_w [NL*DI, 48] fp32 -> [NL*DI, 64] fp16 (cols 48..63 untouched/zero)
__global__ void cvt_dtw_kernel(const float* __restrict__ src,
                               __half* __restrict__ dst) {
    int idx = blockIdx.x * blockDim.x + threadIdx.x;
    int total = kNL * kDI * kDTR;
    if (idx >= total) return;
    int row = idx / kDTR, col = idx - row * kDTR;
    dst[(size_t)row * kDTRp + col] = __float2half_rn(src[idx]);
}

// ---------------- embed gather ----------------
__global__ void embed_kernel(const int* __restrict__ ids,
                             const float* __restrict__ embed,
                             float* __restrict__ x) {
    int idx = blockIdx.x * blockDim.x + threadIdx.x;
    int total = kRows * kD / 4;
    if (idx >= total) return;
    int row = idx / (kD / 4);
    int d4 = idx - row * (kD / 4);
    const float4* src = (const float4*)(embed + (size_t)ids[row] * kD);
    ((float4*)x)[idx] = src[d4];
}

// ---------------- rmsnorm (float4): SPLIT -> fp16 plane; else fp32 ----------
template <bool SPLIT>
__global__ void rmsnorm_kernel(const float* __restrict__ x,
                               const float* __restrict__ w,
                               float* __restrict__ outf,
                               __half* __restrict__ outh) {
    int row = blockIdx.x;
    const float4* xr = (const float4*)(x + (size_t)row * kD);
    float s = 0.f;
    for (int d4 = threadIdx.x; d4 < kD / 4; d4 += blockDim.x) {
        float4 v = xr[d4];
        s = fmaf(v.x, v.x, s);
        s = fmaf(v.y, v.y, s);
        s = fmaf(v.z, v.z, s);
        s = fmaf(v.w, v.w, s);
    }
    s = warp_sum(s);
    __shared__ float sh[8];
    __shared__ float inv_s;
    int wid = threadIdx.x >> 5, lane = threadIdx.x & 31;
    if (lane == 0) sh[wid] = s;
    __syncthreads();
    if (wid == 0) {
        float t = (lane < (blockDim.x >> 5)) ? sh[lane] : 0.f;
        t = warp_sum(t);
        if (lane == 0) inv_s = rsqrtf(t / (float)kD + kEPS);
    }
    __syncthreads();
    float inv = inv_s;
    const float4* wr = (const float4*)w;
    for (int d4 = threadIdx.x; d4 < kD / 4; d4 += blockDim.x) {
        float4 v = xr[d4];
        float4 ww = wr[d4];
        v.x = v.x * inv * ww.x;
        v.y = v.y * inv * ww.y;
        v.z = v.z * inv * ww.z;
        v.w = v.w * inv * ww.w;
        if (SPLIT) {
            __half2* o = (__half2*)(outh + (size_t)row * kD + d4 * 4);
            o[0] = __floats2half2_rn(v.x, v.y);
            o[1] = __floats2half2_rn(v.z, v.w);
        } else {
            ((float4*)(outf + (size_t)row * kD))[d4] = v;
        }
    }
}

// =====================================================================
// fp16 tensor-core GEMM, 3-stage cp.async, single sync/kt, 1 MMA term.
//   C[M,N] = A[M,K] @ Bw[N,K]^T     (A, Bw in fp16)
//   BM in {64,128}, BN=128, BK=32, 256 threads (8 warps: 2 in M, 4 in N)
// EPI 0: store   EPI 1: C += result   EPI 2: softplus(result + bias[n])
// =====================================================================
template <int EPI, int BM>
__global__ __launch_bounds__(256, 2)
void hgemm_ps_kernel(const __half* __restrict__ Ah,
                     const __half* __restrict__ Bh,
                     float* __restrict__ C, int ldc, int K,
                     const float* __restrict__ bias) {
    constexpr int BN = 128, BK = 32;
    constexpr int STR = 40;
    constexpr int WM = BM / 2;
    constexpr int MF = WM / 16;
    constexpr int ASZ = BM * STR;
    constexpr int BSZ = BN * STR;
    constexpr int ACH = BM / 64;
    constexpr int ST = 3;

    extern __shared__ __half sm[];
    __half* As_h = sm;
    __half* Bs_h = As_h + ST * ASZ;

    const int tid = threadIdx.x;
    const int wid = tid >> 5, lane = tid & 31;
    const int bm0 = blockIdx.y * BM;
    const int bn0 = blockIdx.x * BN;
    const int wm = wid & 1;
    const int wn = wid >> 1;

    float acc[MF][4][4];
#pragma unroll
    for (int i = 0; i < MF; i++)
#pragma unroll
        for (int j = 0; j < 4; j++)
#pragma unroll
            for (int v = 0; v < 4; v++) acc[i][j][v] = 0.f;

    auto issue_loads = [&](int buf, int k0) {
#pragma unroll
        for (int u = 0; u < ACH; u++) {
            int id = tid + u * 256;
            int r = id >> 2, c8 = (id & 3) * 8;
            size_t g = (size_t)(bm0 + r) * K + k0 + c8;
            cp16(smem_u32(As_h + buf * ASZ + r * STR + c8), Ah + g);
        }
#pragma unroll
        for (int u = 0; u < 2; u++) {
            int id = tid + u * 256;
            int r = id >> 2, c8 = (id & 3) * 8;
            size_t g = (size_t)(bn0 + r) * K + k0 + c8;
            cp16(smem_u32(Bs_h + buf * BSZ + r * STR + c8), Bh + g);
        }
    };

    const int a_row = wm * WM + (lane & 15);
    const int a_col8 = (lane >> 4) << 3;
    const int b_grp = lane >> 3;
    const int b_row = wn * 32 + ((b_grp >> 1) << 3) + (lane & 7);
    const int b_col8 = (b_grp & 1) << 3;

    const int KT = K / BK;
    issue_loads(0, 0);
    cp_commit();
    if (KT > 1) { issue_loads(1, BK); cp_commit(); }

    for (int kt = 0; kt < KT; kt++) {
        if (kt + 1 < KT) cp_wait<1>(); else cp_wait<0>();
        __syncthreads();
        if (kt + 2 < KT) {
            issue_loads((kt + 2) % ST, (kt + 2) * BK);
            cp_commit();
        }
        const int buf = kt % ST;

#pragma unroll
        for (int kk = 0; kk < 2; kk++) {
            uint32_t ah[MF][4];
            uint32_t bh[4][2];
#pragma unroll
            for (int i = 0; i < MF; i++) {
                uint32_t off = (uint32_t)(buf * ASZ + (a_row + i * 16) * STR
                                          + kk * 16 + a_col8);
                ldmat_x4(ah[i][0], ah[i][1], ah[i][2], ah[i][3],
                         smem_u32(As_h + off));
            }
#pragma unroll
            for (int jj = 0; jj < 2; jj++) {
                uint32_t off = (uint32_t)(buf * BSZ + (b_row + jj * 16) * STR
                                          + kk * 16 + b_col8);
                ldmat_x4(bh[jj * 2][0], bh[jj * 2][1],
                         bh[jj * 2 + 1][0], bh[jj * 2 + 1][1],
                         smem_u32(Bs_h + off));
            }
#pragma unroll
            for (int i = 0; i < MF; i++)
#pragma unroll
                for (int j = 0; j < 4; j++)
                    mma16816h(acc[i][j], ah[i], bh[j][0], bh[j][1]);
        }
    }

    const int c_row = bm0 + wm * WM + (lane >> 2);
    const int c_col = bn0 + wn * 32 + (lane & 3) * 2;
#pragma unroll
    for (int i = 0; i < MF; i++) {
#pragma unroll
        for (int j = 0; j < 4; j++) {
#pragma unroll
            for (int half = 0; half < 2; half++) {
                int gm = c_row + i * 16 + half * 8;
                int gn = c_col + j * 8;
                float* cp = C + (size_t)gm * ldc + gn;
                float v0 = acc[i][j][half * 2 + 0];
                float v1 = acc[i][j][half * 2 + 1];
                if (EPI == 1) {
                    float2 old = *(const float2*)cp;
                    v0 += old.x; v1 += old.y;
                }
                if (EPI == 2) {
                    v0 += bias[gn];
                    v1 += bias[gn + 1];
                    v0 = fmaxf(v0, 0.f) + log1pf(expf(-fabsf(v0)));
                    v1 = fmaxf(v1, 0.f) + log1pf(expf(-fabsf(v1)));
                }
                *(float2*)cp = make_float2(v0, v1);
            }
        }
    }
}

constexpr int kSmem128 = 3 * (128 * 40 + 128 * 40) * 2;  // 61440
constexpr int kSmem64  = 3 * (64 * 40 + 128 * 40) * 2;   // 46080

// =====================================================================
// x_proj split-K GEMM + reduce (reduce also emits fp16 K-padded dt_r)
// =====================================================================
__global__ void gemm_xproj_splitk(const float* __restrict__ A,
                                  const float* __restrict__ Bw,
                                  float* __restrict__ part) {
    constexpr int BM = 64, BN = 64, BK = 16;
    __shared__ float As[BK][BM + 4];
    __shared__ float Bs[BK][BN + 4];
    const int tid = threadIdx.x;
    const int bm0 = blockIdx.y * BM;
    const int bn0 = blockIdx.x * BN;
    const int zoff = blockIdx.z * kXPKC;
    const int tx = tid & 15;
    const int ty = tid >> 4;
    float acc[4][4] = {};

    for (int k0 = 0; k0 < kXPKC; k0 += BK) {
#pragma unroll
        for (int t = tid; t < BM * BK; t += 256) {
            int m = t >> 4, k = t & 15;
            As[k][m] = A[(size_t)(bm0 + m) * kDI + zoff + k0 + k];
        }
#pragma unroll
        for (int t = tid; t < BN * BK; t += 256) {
            int n = t >> 4, k = t & 15;
            int gn = bn0 + n;
            Bs[k][n] = (gn < kDBC) ? Bw[(size_t)gn * kDI + zoff + k0 + k] : 0.f;
        }
        __syncthreads();
#pragma unroll
        for (int k = 0; k < BK; k++) {
            float a[4], b[4];
#pragma unroll
            for (int i = 0; i < 4; i++) a[i] = As[k][ty * 4 + i];
#pragma unroll
            for (int j = 0; j < 4; j++) b[j] = Bs[k][tx * 4 + j];
#pragma unroll
            for (int i = 0; i < 4; i++)
#pragma unroll
                for (int j = 0; j < 4; j++)
                    acc[i][j] = fmaf(a[i], b[j], acc[i][j]);
        }
        __syncthreads();
    }

    float* base = part + (size_t)blockIdx.z * kRows * kDBC;
#pragma unroll
    for (int i = 0; i < 4; i++) {
        int gm = bm0 + ty * 4 + i;
#pragma unroll
        for (int j = 0; j < 4; j++) {
            int gn = bn0 + tx * 4 + j;
            if (gn < kDBC) base[(size_t)gm * kDBC + gn] = acc[i][j];
        }
    }
}

__global__ void reduce_dbc_kernel(const float* __restrict__ part,
                                  float* __restrict__ dbc,
                                  __half* __restrict__ dtr) {
    int idx = blockIdx.x * blockDim.x + threadIdx.x;
    if (idx >= kRows * kDBC) return;
    float s = 0.f;
#pragma unroll
    for (int z = 0; z < kXPChunks; z++)
        s += part[(size_t)z * kRows * kDBC + idx];
    dbc[idx] = s;
    int row = idx / kDBC, col = idx - row * kDBC;
    if (col < kDTR)
        dtr[(size_t)row * kDTRp + col] = __float2half_rn(s);
}

// ---------------- causal depthwise conv (DC=4) + SiLU, float4 ----------------
__global__ void conv_silu_kernel(const float* __restrict__ xz,
                                 const float* __restrict__ cw,
                                 const float* __restrict__ cb,
                                 float* __restrict__ xc) {
    int idx = blockIdx.x * blockDim.x + threadIdx.x;
    int total = kRows * kDI / 4;
    if (idx >= total) return;
    int i4 = idx % (kDI / 4);
    int r = idx / (kDI / 4);
    int l = r % kL;
    int b = r / kL;
    int i = i4 * 4;

    float4 acc = *(const float4*)(cb + i);
#pragma unroll
    for (int k = 0; k < kDC; k++) {
        int ls = l + k - (kDC - 1);
        if (ls >= 0) {
            const float4 xv = *(const float4*)(xz + ((size_t)(b * kL + ls)) * (2 * kDI) + i);
            acc.x = fmaf(xv.x, cw[(i + 0) * kDC + k], acc.x);
            acc.y = fmaf(xv.y, cw[(i + 1) * kDC + k], acc.y);
            acc.z = fmaf(xv.z, cw[(i + 2) * kDC + k], acc.z);
            acc.w = fmaf(xv.w, cw[(i + 3) * kDC + k], acc.w);
        }
    }
    acc.x = acc.x / (1.f + __expf(-acc.x));
    acc.y = acc.y / (1.f + __expf(-acc.y));
    acc.z = acc.z / (1.f + __expf(-acc.z));
    acc.w = acc.w / (1.f + __expf(-acc.w));
    *(float4*)(xc + (size_t)r * kDI + i) = acc;
}

// =====================================================================
// chunked selective scan — register-state version (128-thread blocks)
// =====================================================================
__global__ __launch_bounds__(128)
void scan_p1(const float* __restrict__ dt,
             const float* __restrict__ xc,
             const float* __restrict__ dbc,
             const float* __restrict__ A_log,
             float* __restrict__ E, float* __restrict__ U) {
    int n = blockIdx.x * blockDim.x + threadIdx.x;
    if (n >= kScanT) return;
    int i = n % kDI;
    int bc = n / kDI;
    int c = bc & (kNCH - 1);
    int b = bc >> 5;

    float a[kDS];
#pragma unroll
    for (int q = 0; q < 4; q++) {
        float4 v = *(const float4*)(A_log + (size_t)i * kDS + q * 4);
        a[q * 4 + 0] = -__expf(v.x);
        a[q * 4 + 1] = -__expf(v.y);
        a[q * 4 + 2] = -__expf(v.z);
        a[q * 4 + 3] = -__expf(v.w);
    }
    float h[kDS], Ep[kDS];
#pragma unroll
    for (int s = 0; s < kDS; s++) { h[s] = 0.f; Ep[s] = 1.f; }

    size_t r0 = (size_t)b * kL + c * kG;
    const float* pdt = dt + r0 * kDI + i;
    const float* pxc = xc + r0 * kDI + i;
    const float* pB  = dbc + r0 * kDBC + kDTR;
    for (int g = 0; g < kG; g++) {
        float dt_t = *pdt, x_t = *pxc;
        float Bv[kDS];
#pragma unroll
        for (int q = 0; q < 4; q++) {
            float4 v = *(const float4*)(pB + q * 4);
            Bv[q * 4 + 0] = v.x; Bv[q * 4 + 1] = v.y;
            Bv[q * 4 + 2] = v.z; Bv[q * 4 + 3] = v.w;
        }
#pragma unroll
        for (int s = 0; s < kDS; s++) {
            float e = __expf(dt_t * a[s]);
            h[s] = fmaf(h[s], e, dt_t * x_t * Bv[s]);
            Ep[s] *= e;
        }
        pdt += kDI; pxc += kDI; pB += kDBC;
    }
    size_t t0 = (size_t)n * kDS;
#pragma unroll
    for (int q = 0; q < 4; q++) {
        *(float4*)(E + t0 + q * 4) = make_float4(Ep[q * 4], Ep[q * 4 + 1],
                                                 Ep[q * 4 + 2], Ep[q * 4 + 3]);
        *(float4*)(U + t0 + q * 4) = make_float4(h[q * 4], h[q * 4 + 1],
                                                 h[q * 4 + 2], h[q * 4 + 3]);
    }
}

__global__ __launch_bounds__(128)
void scan_p2(const float* __restrict__ E,
             const float* __restrict__ U,
             float* __restrict__ H) {
    int t = blockIdx.x * blockDim.x + threadIdx.x;
    int sb = t >> 4;
    int s = t & 15;
    int i = sb % kDI;
    int b = sb / kDI;
    float h = 0.f;
#pragma unroll
    for (int c = 0; c < kNCH; c++) {
        size_t idx = ((((size_t)b * kNCH + c) * kDI + i) << 4) + s;
        H[idx] = h;
        h = fmaf(E[idx], h, U[idx]);
    }
}

__global__ __launch_bounds__(128)
void scan_p3(const float* __restrict__ dt,
             const float* __restrict__ xc,
             const float* __restrict__ dbc,
             const float* __restrict__ xz,
             const float* __restrict__ A_log,
             const float* __restrict__ D_skip,
             const float* __restrict__ H,
             __half* __restrict__ yh) {
    int n = blockIdx.x * blockDim.x + threadIdx.x;
    if (n >= kScanT) return;
    int i = n % kDI;
    int bc = n / kDI;
    int c = bc & (kNCH - 1);
    int b = bc >> 5;

    float a[kDS];
#pragma unroll
    for (int q = 0; q < 4; q++) {
        float4 v = *(const float4*)(A_log + (size_t)i * kDS + q * 4);
        a[q * 4 + 0] = -__expf(v.x);
        a[q * 4 + 1] = -__expf(v.y);
        a[q * 4 + 2] = -__expf(v.z);
        a[q * 4 + 3] = -__expf(v.w);
    }
    const float dsk = D_skip[i];
    float h[kDS];
    size_t t0 = (size_t)n * kDS;
#pragma unroll
    for (int q = 0; q < 4; q++) {
        float4 v = *(const float4*)(H + t0 + q * 4);
        h[q * 4 + 0] = v.x; h[q * 4 + 1] = v.y;
        h[q * 4 + 2] = v.z; h[q * 4 + 3] = v.w;
    }

    size_t r0 = (size_t)b * kL + c * kG;
    const float* pdt = dt + r0 * kDI + i;
    const float* pxc = xc + r0 * kDI + i;
    const float* pB  = dbc + r0 * kDBC + kDTR;
    const float* pC  = dbc + r0 * kDBC + kDTR + kDS;
    const float* pz  = xz + r0 * (2 * kDI) + kDI + i;
    __half* pyh = yh + r0 * kDI + i;
    for (int g = 0; g < kG; g++) {
        float dt_t = *pdt, x_t = *pxc;
        float Bv[kDS], Cv[kDS];
#pragma unroll
        for (int q = 0; q < 4; q++) {
            float4 v = *(const float4*)(pB + q * 4);
            Bv[q * 4 + 0] = v.x; Bv[q * 4 + 1] = v.y;
            Bv[q * 4 + 2] = v.z; Bv[q * 4 + 3] = v.w;
            float4 w = *(const float4*)(pC + q * 4);
            Cv[q * 4 + 0] = w.x; Cv[q * 4 + 1] = w.y;
            Cv[q * 4 + 2] = w.z; Cv[q * 4 + 3] = w.w;
        }
        float tmp[kDS];
#pragma unroll
        for (int s = 0; s < kDS; s++) {
            float e = __expf(dt_t * a[s]);
            h[s] = fmaf(h[s], e, dt_t * x_t * Bv[s]);
            tmp[s] = h[s] * Cv[s];
        }
#pragma unroll
        for (int st = 8; st > 0; st >>= 1)
#pragma unroll
            for (int s = 0; s < st; s++) tmp[s] += tmp[s + st];
        float z = *pz;
        float yy = fmaf(x_t, dsk, tmp[0]);
        yy *= z / (1.f + __expf(-z));
        *pyh = __float2half_rn(yy);

        pdt += kDI; pxc += kDI; pB += kDBC; pC += kDBC;
        pz += 2 * kDI; pyh += kDI;
    }
}

// ---------------- final head ----------------
__global__ void head_kernel(const float* __restrict__ xn,
                            const float* __restrict__ cls_w,
                            const float* __restrict__ cls_b,
                            float* __restrict__ out) {
    int b = blockIdx.x;
    __shared__ float mean[kD];
    for (int d = threadIdx.x; d < kD; d += blockDim.x) {
        float s = 0.f;
        const float* p = xn + ((size_t)b * kL) * kD + d;
        for (int l = 0; l < kL; l++) s += p[(size_t)l * kD];
        mean[d] = s / (float)kL;
    }
    __syncthreads();
    if (threadIdx.x < kNC) {
        int c = threadIdx.x;
        float s = cls_b[c];
        for (int d = 0; d < kD; d++) s = fmaf(mean[d], cls_w[c * kD + d], s);
        out[b * kNC + c] = s;
    }
}

// ---------------- launch ----------------
extern "C" void kernel_launch(void* const* d_in, const int* in_sizes, int n_in,
                              void* d_out, int out_size) {
    const int*   input_ids = (const int*)  d_in[0];
    const float* embed     = (const float*)d_in[1];
    const float* norm_w    = (const float*)d_in[2];
    const float* in_proj_w = (const float*)d_in[3];
    const float* conv_w    = (const float*)d_in[4];
    const float* conv_b    = (const float*)d_in[5];
    const float* x_proj_w  = (const float*)d_in[6];
    const float* dt_proj_w = (const float*)d_in[7];
    const float* dt_proj_b = (const float*)d_in[8];
    const float* A_log     = (const float*)d_in[9];
    const float* D_skip    = (const float*)d_in[10];
    const float* out_proj_w= (const float*)d_in[11];
    const float* norm_f_w  = (const float*)d_in[12];
    const float* cls_w     = (const float*)d_in[13];
    const float* cls_b     = (const float*)d_in[14];
    float* out = (float*)d_out;

    float *px, *pxn, *pxz, *pxc, *pdbc, *pdbp, *pdt, *pE, *pU, *pH;
    __half *pwinh, *pwouth, *pxnh, *pyh, *pdtr, *pdtwh;
    cudaGetSymbolAddress((void**)&px,    g_x);
    cudaGetSymbolAddress((void**)&pxn,   g_xn);
    cudaGetSymbolAddress((void**)&pxz,   g_xz);
    cudaGetSymbolAddress((void**)&pxc,   g_xc);
    cudaGetSymbolAddress((void**)&pdbc,  g_dbc);
    cudaGetSymbolAddress((void**)&pdbp,  g_dbp);
    cudaGetSymbolAddress((void**)&pdt,   g_dt);
    cudaGetSymbolAddress((void**)&pE,    g_E);
    cudaGetSymbolAddress((void**)&pU,    g_U);
    cudaGetSymbolAddress((void**)&pH,    g_H);
    cudaGetSymbolAddress((void**)&pwinh, g_winh);
    cudaGetSymbolAddress((void**)&pwouth,g_wouth);
    cudaGetSymbolAddress((void**)&pxnh,  g_xnh);
    cudaGetSymbolAddress((void**)&pyh,   g_yh);
    cudaGetSymbolAddress((void**)&pdtr,  g_dtr);
    cudaGetSymbolAddress((void**)&pdtwh, g_dtwh);

    cudaFuncSetAttribute(hgemm_ps_kernel<0, 128>,
                         cudaFuncAttributeMaxDynamicSharedMemorySize, kSmem128);
    cudaFuncSetAttribute(hgemm_ps_kernel<1, 64>,
                         cudaFuncAttributeMaxDynamicSharedMemorySize, kSmem64);
    cudaFuncSetAttribute(hgemm_ps_kernel<2, 64>,
                         cudaFuncAttributeMaxDynamicSharedMemorySize, kSmem64);

    const int sBlocks = kScanT / 128;             // 768
    const int p2Blocks = (kB * kDI * kDS) / 128;  // 384

    // launch 0: embed, 1: cvt_in, 2: rmsnorm(L0), 3: in_proj <- ncu capture
    {
        int total = kRows * kD / 4;
        embed_kernel<<<(total + 255) / 256, 256>>>(input_ids, embed, px);
    }
    {
        int n4 = kInWN / 4;
        cvt_f16_kernel<<<(n4 + 255) / 256, 256>>>(in_proj_w, pwinh, n4);
    }

    for (int l = 0; l < kNL; l++) {
        const float* w_norm = norm_w    + (size_t)l * kD;
        const float* w_cw   = conv_w    + (size_t)l * kDI * kDC;
        const float* w_cb   = conv_b    + (size_t)l * kDI;
        const float* w_xp   = x_proj_w  + (size_t)l * kDBC * kDI;
        const float* w_dtb  = dt_proj_b + (size_t)l * kDI;
        const float* w_Al   = A_log     + (size_t)l * kDI * kDS;
        const float* w_Dsk  = D_skip    + (size_t)l * kDI;
        const __half* w_inh  = pwinh  + (size_t)l * 2 * kDI * kD;
        const __half* w_outh = pwouth + (size_t)l * kD * kDI;
        const __half* w_dtwh = pdtwh  + (size_t)l * kDI * kDTRp;

        // rmsnorm -> fp16 plane
        rmsnorm_kernel<true><<<kRows, 192>>>(px, w_norm, nullptr, pxnh);

        // in_proj: fp16 single-term, 128x128 tiles, 3-stage pipeline
        {
            dim3 grid(2 * kDI / 128, kRows / 128);   // (24,16)
            hgemm_ps_kernel<0, 128><<<grid, 256, kSmem128>>>(
                pxnh, w_inh, pxz, 2 * kDI, kD, nullptr);
        }

        // conv + silu (float4)
        {
            int total = kRows * kDI / 4;
            conv_silu_kernel<<<(total + 255) / 256, 256>>>(pxz, w_cw, w_cb, pxc);
        }

        // x_proj split-K; reduce also emits fp16 dt_r (K-padded)
        {
            dim3 grid(2, kRows / 64, kXPChunks);
            gemm_xproj_splitk<<<grid, 256>>>(pxc, w_xp, pdbp);
            int total = kRows * kDBC;
            reduce_dbc_kernel<<<(total + 255) / 256, 256>>>(pdbp, pdbc, pdtr);
        }

        // convert dt_proj_w once (all layers), before first use
        if (l == 0) {
            int total = kNL * kDI * kDTR;
            cvt_dtw_kernel<<<(total + 255) / 256, 256>>>(dt_proj_w, pdtwh);
        }

        // dt: fp16 tensor cores, K=64 (padded), softplus+bias epilogue
        {
            dim3 grid(kDI / 128, kRows / 64);        // (12,32)
            hgemm_ps_kernel<2, 64><<<grid, 256, kSmem64>>>(
                pdtr, w_dtwh, pdt, kDI, kDTRp, w_dtb);
        }

        // chunked selective scan (register-state, 128-thread blocks)
        scan_p1<<<sBlocks, 128>>>(pdt, pxc, pdbc, w_Al, pE, pU);
        scan_p2<<<p2Blocks, 128>>>(pE, pU, pH);
        scan_p3<<<sBlocks, 128>>>(pdt, pxc, pdbc, pxz, w_Al, w_Dsk, pH, pyh);

        // convert out_proj weights once, before first use
        if (l == 0) {
            int n4 = kOutWN / 4;
            cvt_f16_kernel<<<(n4 + 255) / 256, 256>>>(out_proj_w, pwouth, n4);
        }

        // out_proj + residual: fp16 single-term, 64x128 tiles
        {
            dim3 grid(kD / 128, kRows / 64);         // (6,32)
            hgemm_ps_kernel<1, 64><<<grid, 256, kSmem64>>>(
                pyh, w_outh, px, kD, kDI, nullptr);
        }
    }

    rmsnorm_kernel<false><<<kRows, 192>>>(px, norm_f_w, pxn, nullptr);
    head_kernel<<<kB, 256>>>(pxn, cls_w, cls_b, out);
}